// round 9
// baseline (speedup 1.0000x reference)
#include <cuda_runtime.h>
#include <cuda_bf16.h>
#include <cstdint>
#include <cstddef>

#define LSEQ 4096
#define LH   2048
#define NBH  128

// ------------------------------------------------------------- gmem scratch
__device__ __nv_bfloat16 g_Fu_hi[64 * LH], g_Fu_lo[64 * LH];   // fwd basis even-f rows
__device__ __nv_bfloat16 g_Fv_hi[64 * LH], g_Fv_lo[64 * LH];   // fwd basis odd-f rows
__device__ __nv_bfloat16 g_Gte_hi[LH * 64], g_Gte_lo[LH * 64]; // inv basis even parity
__device__ __nv_bfloat16 g_Gto_hi[LH * 64], g_Gto_lo[LH * 64]; // inv basis odd parity
__device__ float         g_Xp[2 * NBH * 64 * 128];             // [khalf][bh][e][f2]
__device__ __nv_bfloat16 g_Ce_hi[NBH * 64 * 64], g_Ce_lo[NBH * 64 * 64];
__device__ __nv_bfloat16 g_Co_hi[NBH * 64 * 64], g_Co_lo[NBH * 64 * 64];

// ------------------------------------------------------------- helpers
__device__ __forceinline__ uint32_t smem_u32(const void* p) {
    uint32_t a;
    asm("{ .reg .u64 t; cvta.to.shared.u64 t, %1; cvt.u32.u64 %0, t; }" : "=r"(a) : "l"(p));
    return a;
}
__device__ __forceinline__ void split_bf16(float x, __nv_bfloat16& hi, __nv_bfloat16& lo) {
    hi = __float2bfloat16(x);
    lo = __float2bfloat16(x - __bfloat162float(hi));
}
__device__ __forceinline__ void ldsm4(uint32_t* r, uint32_t addr) {
    asm volatile("ldmatrix.sync.aligned.m8n8.x4.shared.b16 {%0,%1,%2,%3}, [%4];"
                 : "=r"(r[0]), "=r"(r[1]), "=r"(r[2]), "=r"(r[3]) : "r"(addr));
}
__device__ __forceinline__ void ldsm4t(uint32_t* r, uint32_t addr) {
    asm volatile("ldmatrix.sync.aligned.m8n8.x4.trans.shared.b16 {%0,%1,%2,%3}, [%4];"
                 : "=r"(r[0]), "=r"(r[1]), "=r"(r[2]), "=r"(r[3]) : "r"(addr));
}
__device__ __forceinline__ void mma16816(float* d, const uint32_t* a, const uint32_t* b) {
    asm volatile("mma.sync.aligned.m16n8k16.row.col.f32.bf16.bf16.f32 "
                 "{%0,%1,%2,%3}, {%4,%5,%6,%7}, {%8,%9}, {%0,%1,%2,%3};"
                 : "+f"(d[0]), "+f"(d[1]), "+f"(d[2]), "+f"(d[3])
                 : "r"(a[0]), "r"(a[1]), "r"(a[2]), "r"(a[3]), "r"(b[0]), "r"(b[1]));
}
#define CP16(sa, gp) asm volatile("cp.async.cg.shared.global [%0], [%1], 16;" \
                                  :: "r"((uint32_t)(sa)), "l"(gp) : "memory")
#define CP_COMMIT()  asm volatile("cp.async.commit_group;" ::: "memory")
#define CP_WAIT0()   asm volatile("cp.async.wait_group 0;" ::: "memory")
#define CP_WAIT1()   asm volatile("cp.async.wait_group 1;" ::: "memory")

// ---------------------------------------------------------------- basis init
__global__ void init_basis_kernel() {
    int idx = blockIdx.x * 256 + threadIdx.x;      // < 131072
    {   // Fu/Fv rows ru = 2*fe + c (c=0 cos, c=1 -sin), half domain
        int ru = idx >> 11, l = idx & 2047;
        int fe = ru >> 1, c = ru & 1;
        float s, cs;
        __nv_bfloat16 hi, lo;
        sincospif((float)((l * (2 * fe)) & 4095) / 2048.0f, &s, &cs);
        split_bf16(c ? -s : cs, hi, lo);
        g_Fu_hi[ru * LH + l] = hi;  g_Fu_lo[ru * LH + l] = lo;
        sincospif((float)((l * (2 * fe + 1)) & 4095) / 2048.0f, &s, &cs);
        split_bf16(c ? -s : cs, hi, lo);
        g_Fv_hi[ru * LH + l] = hi;  g_Fv_lo[ru * LH + l] = lo;
    }
    {   // Gte/Gto: [l][kk=2*fe+c], c=0 cos, c=1 +sin
        int l = idx >> 6, kk = idx & 63;
        int fe = kk >> 1, c = kk & 1;
        float s, cs;
        __nv_bfloat16 hi, lo;
        sincospif((float)((l * (2 * fe)) & 4095) / 2048.0f, &s, &cs);
        split_bf16(c ? s : cs, hi, lo);
        g_Gte_hi[l * 64 + kk] = hi;  g_Gte_lo[l * 64 + kk] = lo;
        sincospif((float)((l * (2 * fe + 1)) & 4095) / 2048.0f, &s, &cs);
        split_bf16(c ? s : cs, hi, lo);
        g_Gto_hi[l * 64 + kk] = hi;  g_Gto_lo[l * 64 + kk] = lo;
    }
}

// ---------------------------------------------------------------- Stage 1: DFT
// Fused q->butterfly->split->HMMA. CTA = (khalf, bh): 16 chunks of 64 half-l each.
// Partial spectra to g_Xp[khalf]; mix sums the two partials.
#define D_ARR  9216                  // 64 rows * 144B
#define F_STG  (4 * D_ARR)
#define DFT_SMEM (4 * F_STG)         // 147456

__global__ __launch_bounds__(256) void dft_fused_kernel(const float* __restrict__ q) {
    extern __shared__ char smd[];
    const uint32_t sb = smem_u32(smd);
    const int bh = blockIdx.x & 127, khalf = blockIdx.x >> 7;
    const int b = bh >> 3, h = bh & 7;
    const int t = threadIdx.x, w = t >> 5, lane = t & 31;
    const int grp = w >> 2, wr = w & 3;
    const float* qb = q + ((size_t)b * LSEQ * 8 + h) * 64;

    const __nv_bfloat16* srcF[4] = { g_Fu_hi, g_Fu_lo, g_Fv_hi, g_Fv_lo };

    const int ql = t >> 4, qe4 = (t & 15) * 4;
    float4 ra[4], rb[4];
    auto LDGQ = [&](int l0) {
        #pragma unroll
        for (int ps = 0; ps < 4; ++ps) {
            const float* p = qb + (size_t)(l0 + ql + ps * 16) * 512 + qe4;
            ra[ps] = *(const float4*)p;
            rb[ps] = *(const float4*)(p + (size_t)LH * 512);
        }
    };
    auto issueF = [&](int c, uint32_t stg) {
        const size_t k0 = (size_t)c * 64;
        #pragma unroll
        for (int i = 0; i < 8; ++i) {
            int arr = i >> 1;
            int idx = ((i & 1) << 8) + t;
            int row = idx >> 3, kg = (idx & 7) * 8;
            CP16(stg + arr * D_ARR + (uint32_t)row * 144 + kg * 2,
                 srcF[arr] + (size_t)row * LH + k0 + kg);
        }
        CP_COMMIT();
    };
    auto convert = [&](uint32_t uvb) {
        #pragma unroll
        for (int ps = 0; ps < 4; ++ps) {
            int l = ql + ps * 16;
            uint32_t ad = uvb + (uint32_t)l * 144 + (t & 15) * 8;
            float4 a = ra[ps], bb = rb[ps];
            float uv[2][4] = {{a.x + bb.x, a.y + bb.y, a.z + bb.z, a.w + bb.w},
                              {a.x - bb.x, a.y - bb.y, a.z - bb.z, a.w - bb.w}};
            #pragma unroll
            for (int s = 0; s < 2; ++s) {
                union { uint32_t u[2]; __nv_bfloat16 x[4]; } H, L;
                #pragma unroll
                for (int j = 0; j < 4; ++j) {
                    __nv_bfloat16 hi, lo;
                    split_bf16(uv[s][j], hi, lo);
                    H.x[j] = hi;  L.x[j] = lo;
                }
                *(uint2*)(smd + (ad - sb) + s * 2 * D_ARR)         = make_uint2(H.u[0], H.u[1]);
                *(uint2*)(smd + (ad - sb) + s * 2 * D_ARR + D_ARR) = make_uint2(L.u[0], L.u[1]);
            }
        }
    };

    const uint32_t aoff = (uint32_t)(wr * 16 + (lane & 15)) * 144 + (lane >> 4) * 16;
    const uint32_t boff = (uint32_t)(lane & 15) * 144 + (lane >> 4) * 16;

    float acc[8][4];
    #pragma unroll
    for (int i = 0; i < 8; ++i)
        #pragma unroll
        for (int j = 0; j < 4; ++j) acc[i][j] = 0.f;

    const int c0 = khalf * 16, c1 = c0 + 16;
    LDGQ(c0 * 64);
    issueF(c0, sb);
    for (int c = c0; c < c1; ++c) {
        const uint32_t uvb = sb + 2 * F_STG + (uint32_t)(c & 1) * F_STG;
        convert(uvb);
        if (c < c1 - 1) {
            LDGQ((c + 1) * 64);
            issueF(c + 1, sb + (uint32_t)((c + 1) & 1) * F_STG);
            CP_WAIT1();
        } else CP_WAIT0();
        __syncthreads();
        const uint32_t fst = sb + (uint32_t)(c & 1) * F_STG;
        const uint32_t aHi = fst + grp * (2 * D_ARR) + aoff, aLo = aHi + D_ARR;
        const uint32_t bHi = uvb + grp * (2 * D_ARR) + boff, bLo = bHi + D_ARR;
        #pragma unroll
        for (int ks = 0; ks < 4; ++ks) {
            uint32_t ah[4], al[4];
            ldsm4(ah, aHi + ks * 32);
            ldsm4(al, aLo + ks * 32);
            #pragma unroll
            for (int j = 0; j < 4; ++j) {
                uint32_t bh_[4], bl_[4];
                ldsm4t(bh_, bHi + ks * 2304 + j * 32);
                ldsm4t(bl_, bLo + ks * 2304 + j * 32);
                mma16816(acc[2 * j],     ah, bh_);
                mma16816(acc[2 * j],     ah, bl_);
                mma16816(acc[2 * j],     al, bh_);
                mma16816(acc[2 * j + 1], ah, bh_ + 2);
                mma16816(acc[2 * j + 1], ah, bl_ + 2);
                mma16816(acc[2 * j + 1], al, bh_ + 2);
            }
        }
        __syncthreads();
    }

    const int g = lane >> 2, q4 = lane & 3;
    float* xb = g_Xp + (size_t)khalf * (NBH * 8192) + (size_t)bh * 8192;
    const int r0 = wr * 16 + g, r1 = r0 + 8;
    const int f2a = 2 * r0 - (r0 & 1) + 2 * grp;
    const int f2b = 2 * r1 - (r1 & 1) + 2 * grp;
    #pragma unroll
    for (int j = 0; j < 8; ++j) {
        int e0 = j * 8 + q4 * 2;
        xb[e0 * 128 + f2a]       = acc[j][0];
        xb[(e0 + 1) * 128 + f2a] = acc[j][1];
        xb[e0 * 128 + f2b]       = acc[j][2];
        xb[(e0 + 1) * 128 + f2b] = acc[j][3];
    }
}

// ---------------------------------------------------------------- Stage 2: mix
#define MIX_SMEM 98304       // Ws_r 32K | Ws_i 32K | Xs 32K
__global__ __launch_bounds__(256) void mix_kernel(const float* __restrict__ wr,
                                                  const float* __restrict__ wi) {
    extern __shared__ char sm[];
    float* Ws_r = (float*)sm;
    float* Ws_i = (float*)(sm + 32768);
    float* Xs   = (float*)(sm + 65536);
    const int h = blockIdx.x & 7, og = (blockIdx.x >> 3) & 7, bq = blockIdx.x >> 6;
    const int t = threadIdx.x;
    const int f2 = t & 31, ol = t >> 5;

    float acc[4][4];
    #pragma unroll
    for (int i = 0; i < 4; ++i)
        #pragma unroll
        for (int j = 0; j < 4; ++j) acc[i][j] = 0.f;

    for (int e0 = 0; e0 < 64; e0 += 16) {
        __syncthreads();
        #pragma unroll
        for (int i = 0; i < 8; ++i) {
            int c = t + i * 256;
            int row = c >> 4, m4 = (c & 15) * 4;
            int e = row >> 3, o = row & 7;
            size_t g = (((size_t)h * 64 + e0 + e) * 64 + og * 8 + o) * 64 + m4;
            *(float4*)&Ws_r[(e * 8 + o) * 64 + m4] = *(const float4*)&wr[g];
            *(float4*)&Ws_i[(e * 8 + o) * 64 + m4] = *(const float4*)&wi[g];
        }
        #pragma unroll
        for (int i = 0; i < 8; ++i) {
            int c = t + i * 256;
            int row = c >> 5, f4 = (c & 31) * 4;
            int b = row >> 4, e = row & 15;
            int bh = (bq * 4 + b) * 8 + h;
            size_t xoff = (size_t)bh * 8192 + (e0 + e) * 128 + f4;
            float4 x0 = *(const float4*)&g_Xp[xoff];
            float4 x1 = *(const float4*)&g_Xp[(size_t)NBH * 8192 + xoff];
            *(float4*)&Xs[(b * 16 + e) * 128 + f4] =
                make_float4(x0.x + x1.x, x0.y + x1.y, x0.z + x1.z, x0.w + x1.w);
        }
        __syncthreads();
        #pragma unroll 4
        for (int e = 0; e < 16; ++e) {
            float2 w_r = *(float2*)&Ws_r[(e * 8 + ol) * 64 + 2 * f2];
            float2 w_i = *(float2*)&Ws_i[(e * 8 + ol) * 64 + 2 * f2];
            #pragma unroll
            for (int b = 0; b < 4; ++b) {
                float4 x = *(float4*)&Xs[(b * 16 + e) * 128 + 4 * f2];
                acc[b][0] += x.x * w_r.x - x.y * w_i.x;
                acc[b][1] += x.x * w_i.x + x.y * w_r.x;
                acc[b][2] += x.z * w_r.y - x.w * w_i.y;
                acc[b][3] += x.z * w_i.y + x.w * w_r.y;
            }
        }
    }
    const float a0 = (f2 == 0) ? (1.0f / 4096.0f) : (2.0f / 4096.0f);
    const float a1 = 2.0f / 4096.0f;
    #pragma unroll
    for (int b = 0; b < 4; ++b) {
        size_t row = (size_t)((bq * 4 + b) * 8 + h) * 64 + og * 8 + ol;
        float ve0 = a0 * acc[b][0], ve1 = -a0 * acc[b][1];
        float vo0 = a1 * acc[b][2], vo1 = -a1 * acc[b][3];
        union { uint32_t u; __nv_bfloat16 x[2]; } p;
        __nv_bfloat16 hi, lo, hi2, lo2;
        split_bf16(ve0, hi, lo);  split_bf16(ve1, hi2, lo2);
        p.x[0] = hi;  p.x[1] = hi2;  *(uint32_t*)&g_Ce_hi[row * 64 + 2 * f2] = p.u;
        p.x[0] = lo;  p.x[1] = lo2;  *(uint32_t*)&g_Ce_lo[row * 64 + 2 * f2] = p.u;
        split_bf16(vo0, hi, lo);  split_bf16(vo1, hi2, lo2);
        p.x[0] = hi;  p.x[1] = hi2;  *(uint32_t*)&g_Co_hi[row * 64 + 2 * f2] = p.u;
        p.x[0] = lo;  p.x[1] = lo2;  *(uint32_t*)&g_Co_lo[row * 64 + 2 * f2] = p.u;
    }
}

// ---------------------------------------------------------------- Stage 3: iDFT
// CTA = (bh, lq). Warps 0-3: E GEMM, warps 4-7: O GEMM (concurrent).
// Epilogue staged in smem (aliases consumed G stage) -> coalesced float4 stores.
#define IA_ARR 9216                  // 64 rows * 144B
#define IA_SZ  (4 * IA_ARR)          // 36864
#define IG_ARR 18432                 // 128 rows * 144B
#define IG_SZ  (4 * IG_ARR)          // 73728
#define IDFT_SMEM (IA_SZ + 2 * IG_SZ)   // 184320
#define EPAD 132                     // staging row stride (floats)

__global__ __launch_bounds__(256) void idft_mma_kernel(float* __restrict__ out) {
    extern __shared__ char smi[];
    const uint32_t sb = smem_u32(smi);
    const int bh = blockIdx.x & 127, lq = blockIdx.x >> 7;
    const int t = threadIdx.x, w = t >> 5, lane = t & 31;
    const int grp = w >> 2, w4 = w & 3;
    const size_t pC = (size_t)bh * 64 * 64;

    const __nv_bfloat16* srcA[4] = { g_Ce_hi + pC, g_Ce_lo + pC, g_Co_hi + pC, g_Co_lo + pC };
    const __nv_bfloat16* srcG[4] = { g_Gte_hi, g_Gte_lo, g_Gto_hi, g_Gto_lo };

    auto issueG = [&](int lc, uint32_t stg) {
        const size_t lG = (size_t)lc * 128 * 64;
        #pragma unroll
        for (int i = 0; i < 16; ++i) {
            int arr = i >> 2;
            int idx = ((i & 3) << 8) + t;
            int row = idx >> 3, kg = (idx & 7) * 8;
            CP16(stg + arr * IG_ARR + (uint32_t)row * 144 + kg * 2,
                 srcG[arr] + lG + (size_t)row * 64 + kg);
        }
    };

    // A (64 rows x 64 k, 4 arrays) + G(lq*4), one group
    #pragma unroll
    for (int i = 0; i < 8; ++i) {
        int arr = i >> 1;
        int idx = ((i & 1) << 8) + t;
        int row = idx >> 3, kg = (idx & 7) * 8;
        CP16(sb + arr * IA_ARR + (uint32_t)row * 144 + kg * 2,
             srcA[arr] + (size_t)row * 64 + kg);
    }
    issueG(lq * 4, sb + IA_SZ);
    CP_COMMIT();

    const uint32_t aoff = (uint32_t)(w4 * 16 + (lane & 15)) * 144 + (lane >> 4) * 16;
    const uint32_t boff = (uint32_t)((lane >> 4) * 8 + (lane & 7)) * 144 + ((lane >> 3) & 1) * 16;
    const int g = lane >> 2, q4 = lane & 3;
    const int col4 = (lane) * 4;     // combine-pass col (0..124)
    const int rb8 = t >> 5;          // combine-pass row base

    for (int cc = 0; cc < 4; ++cc) {
        const int lc = lq * 4 + cc;
        const uint32_t gst = sb + IA_SZ + (uint32_t)(cc & 1) * IG_SZ;
        if (cc < 3) {
            issueG(lc + 1, sb + IA_SZ + (uint32_t)((cc + 1) & 1) * IG_SZ);
            CP_COMMIT();
            CP_WAIT1();
        } else CP_WAIT0();
        __syncthreads();

        float acc[16][4];
        #pragma unroll
        for (int i = 0; i < 16; ++i)
            #pragma unroll
            for (int j = 0; j < 4; ++j) acc[i][j] = 0.f;

        const uint32_t aHi = sb + grp * (2 * IA_ARR) + aoff, aLo = aHi + IA_ARR;
        const uint32_t bHi = gst + grp * (2 * IG_ARR) + boff, bLo = bHi + IG_ARR;
        #pragma unroll
        for (int ks = 0; ks < 4; ++ks) {
            uint32_t ah[4], al[4];
            ldsm4(ah, aHi + ks * 32);
            ldsm4(al, aLo + ks * 32);
            #pragma unroll
            for (int j = 0; j < 8; ++j) {
                uint32_t bh_[4], bl_[4];
                ldsm4(bh_, bHi + j * 2304 + ks * 32);
                ldsm4(bl_, bLo + j * 2304 + ks * 32);
                mma16816(acc[2 * j],     ah, bh_);
                mma16816(acc[2 * j],     ah, bl_);
                mma16816(acc[2 * j],     al, bh_);
                mma16816(acc[2 * j + 1], ah, bh_ + 2);
                mma16816(acc[2 * j + 1], ah, bl_ + 2);
                mma16816(acc[2 * j + 1], al, bh_ + 2);
            }
        }
        __syncthreads();        // all warps done reading stage gst

        // stage accs as fp32 into the consumed G stage: E at +0, O at +33792
        float* stgf = (float*)(smi + (gst - sb) + grp * 33792);
        const int r0 = w4 * 16 + g, r1 = r0 + 8;
        #pragma unroll
        for (int j = 0; j < 16; ++j) {
            int col = j * 8 + q4 * 2;
            stgf[r0 * EPAD + col]     = acc[j][0];
            stgf[r0 * EPAD + col + 1] = acc[j][1];
            stgf[r1 * EPAD + col]     = acc[j][2];
            stgf[r1 * EPAD + col + 1] = acc[j][3];
        }
        __syncthreads();

        // combine + coalesced store
        float* Ebuf = (float*)(smi + (gst - sb));
        float* Obuf = Ebuf + 8448;   // 33792 bytes
        #pragma unroll
        for (int i = 0; i < 8; ++i) {
            int r = rb8 + 8 * i;
            float4 E = *(float4*)&Ebuf[r * EPAD + col4];
            float4 O = *(float4*)&Obuf[r * EPAD + col4];
            float* op = out + ((size_t)bh * 64 + r) * LSEQ + lc * 128 + col4;
            *(float4*)op = make_float4(E.x + O.x, E.y + O.y, E.z + O.z, E.w + O.w);
            *(float4*)(op + LH) = make_float4(E.x - O.x, E.y - O.y, E.z - O.z, E.w - O.w);
        }
        __syncthreads();        // protect stage region before next cp.async reuse
    }
}

// ---------------------------------------------------------------------------
extern "C" void kernel_launch(void* const* d_in, const int* in_sizes, int n_in,
                              void* d_out, int out_size) {
    const float* q = (const float*)d_in[0];
    const float* wr = nullptr;
    const float* wi = nullptr;
    for (int i = 0; i < n_in; ++i) {
        if (in_sizes[i] == 8 * 64 * 64 * 64) {
            if (!wr) wr = (const float*)d_in[i];
            else if (!wi) wi = (const float*)d_in[i];
        }
    }
    float* out = (float*)d_out;

    cudaFuncSetAttribute(dft_fused_kernel, cudaFuncAttributeMaxDynamicSharedMemorySize, DFT_SMEM);
    cudaFuncSetAttribute(mix_kernel,       cudaFuncAttributeMaxDynamicSharedMemorySize, MIX_SMEM);
    cudaFuncSetAttribute(idft_mma_kernel,  cudaFuncAttributeMaxDynamicSharedMemorySize, IDFT_SMEM);

    init_basis_kernel<<<512, 256>>>();
    dft_fused_kernel<<<256, 256, DFT_SMEM>>>(q);
    mix_kernel<<<256, 256, MIX_SMEM>>>(wr, wi);
    idft_mma_kernel<<<512, 256, IDFT_SMEM>>>(out);
}

// round 10
// speedup vs baseline: 1.0983x; 1.0983x over previous
#include <cuda_runtime.h>
#include <cuda_bf16.h>
#include <cstdint>
#include <cstddef>

#define LSEQ 4096
#define LH   2048
#define NBH  128

// ------------------------------------------------------------- gmem scratch
__device__ __nv_bfloat16 g_Fu_hi[64 * LH], g_Fu_lo[64 * LH];   // fwd basis even-f rows
__device__ __nv_bfloat16 g_Fv_hi[64 * LH], g_Fv_lo[64 * LH];   // fwd basis odd-f rows
__device__ __nv_bfloat16 g_Gte_hi[LH * 64], g_Gte_lo[LH * 64]; // inv basis even parity
__device__ __nv_bfloat16 g_Gto_hi[LH * 64], g_Gto_lo[LH * 64]; // inv basis odd parity
__device__ float         g_X[NBH * 64 * 128];                  // [bh][e][f2]
__device__ __nv_bfloat16 g_Ce_hi[NBH * 64 * 64], g_Ce_lo[NBH * 64 * 64];
__device__ __nv_bfloat16 g_Co_hi[NBH * 64 * 64], g_Co_lo[NBH * 64 * 64];

// ------------------------------------------------------------- helpers
__device__ __forceinline__ uint32_t smem_u32(const void* p) {
    uint32_t a;
    asm("{ .reg .u64 t; cvta.to.shared.u64 t, %1; cvt.u32.u64 %0, t; }" : "=r"(a) : "l"(p));
    return a;
}
__device__ __forceinline__ void split_bf16(float x, __nv_bfloat16& hi, __nv_bfloat16& lo) {
    hi = __float2bfloat16(x);
    lo = __float2bfloat16(x - __bfloat162float(hi));
}
__device__ __forceinline__ void ldsm4(uint32_t* r, uint32_t addr) {
    asm volatile("ldmatrix.sync.aligned.m8n8.x4.shared.b16 {%0,%1,%2,%3}, [%4];"
                 : "=r"(r[0]), "=r"(r[1]), "=r"(r[2]), "=r"(r[3]) : "r"(addr));
}
__device__ __forceinline__ void ldsm4t(uint32_t* r, uint32_t addr) {
    asm volatile("ldmatrix.sync.aligned.m8n8.x4.trans.shared.b16 {%0,%1,%2,%3}, [%4];"
                 : "=r"(r[0]), "=r"(r[1]), "=r"(r[2]), "=r"(r[3]) : "r"(addr));
}
__device__ __forceinline__ void mma16816(float* d, const uint32_t* a, const uint32_t* b) {
    asm volatile("mma.sync.aligned.m16n8k16.row.col.f32.bf16.bf16.f32 "
                 "{%0,%1,%2,%3}, {%4,%5,%6,%7}, {%8,%9}, {%0,%1,%2,%3};"
                 : "+f"(d[0]), "+f"(d[1]), "+f"(d[2]), "+f"(d[3])
                 : "r"(a[0]), "r"(a[1]), "r"(a[2]), "r"(a[3]), "r"(b[0]), "r"(b[1]));
}
#define CP16(sa, gp) asm volatile("cp.async.cg.shared.global [%0], [%1], 16;" \
                                  :: "r"((uint32_t)(sa)), "l"(gp) : "memory")
#define CP_COMMIT()  asm volatile("cp.async.commit_group;" ::: "memory")
#define CP_WAIT0()   asm volatile("cp.async.wait_group 0;" ::: "memory")
#define CP_WAIT1()   asm volatile("cp.async.wait_group 1;" ::: "memory")

// ---------------------------------------------------------------- basis init
__global__ void init_basis_kernel() {
    int idx = blockIdx.x * 256 + threadIdx.x;      // < 131072
    {   // Fu/Fv rows ru = 2*fe + c (c=0 cos, c=1 -sin), half domain
        int ru = idx >> 11, l = idx & 2047;
        int fe = ru >> 1, c = ru & 1;
        float s, cs;
        __nv_bfloat16 hi, lo;
        sincospif((float)((l * (2 * fe)) & 4095) / 2048.0f, &s, &cs);
        split_bf16(c ? -s : cs, hi, lo);
        g_Fu_hi[ru * LH + l] = hi;  g_Fu_lo[ru * LH + l] = lo;
        sincospif((float)((l * (2 * fe + 1)) & 4095) / 2048.0f, &s, &cs);
        split_bf16(c ? -s : cs, hi, lo);
        g_Fv_hi[ru * LH + l] = hi;  g_Fv_lo[ru * LH + l] = lo;
    }
    {   // Gte/Gto: [l][kk=2*fe+c], c=0 cos, c=1 +sin
        int l = idx >> 6, kk = idx & 63;
        int fe = kk >> 1, c = kk & 1;
        float s, cs;
        __nv_bfloat16 hi, lo;
        sincospif((float)((l * (2 * fe)) & 4095) / 2048.0f, &s, &cs);
        split_bf16(c ? s : cs, hi, lo);
        g_Gte_hi[l * 64 + kk] = hi;  g_Gte_lo[l * 64 + kk] = lo;
        sincospif((float)((l * (2 * fe + 1)) & 4095) / 2048.0f, &s, &cs);
        split_bf16(c ? s : cs, hi, lo);
        g_Gto_hi[l * 64 + kk] = hi;  g_Gto_lo[l * 64 + kk] = lo;
    }
}

// ---------------------------------------------------------------- Stage 1: DFT
// Fused q->butterfly->split->HMMA (R8 structure: CTA/bh, 32 chunks of 64 half-l).
#define D_ARR  9216                  // 64 rows * 144B
#define F_STG  (4 * D_ARR)
#define DFT_SMEM (4 * F_STG)         // 147456

__global__ __launch_bounds__(256) void dft_fused_kernel(const float* __restrict__ q) {
    extern __shared__ char smd[];
    const uint32_t sb = smem_u32(smd);
    const int bh = blockIdx.x, b = bh >> 3, h = bh & 7;
    const int t = threadIdx.x, w = t >> 5, lane = t & 31;
    const int grp = w >> 2, wr = w & 3;
    const float* qb = q + ((size_t)b * LSEQ * 8 + h) * 64;

    const __nv_bfloat16* srcF[4] = { g_Fu_hi, g_Fu_lo, g_Fv_hi, g_Fv_lo };

    const int ql = t >> 4, qe4 = (t & 15) * 4;
    float4 ra[4], rb[4];
    auto LDGQ = [&](int l0) {
        #pragma unroll
        for (int ps = 0; ps < 4; ++ps) {
            const float* p = qb + (size_t)(l0 + ql + ps * 16) * 512 + qe4;
            ra[ps] = *(const float4*)p;
            rb[ps] = *(const float4*)(p + (size_t)LH * 512);
        }
    };
    auto issueF = [&](int c, uint32_t stg) {
        const size_t k0 = (size_t)c * 64;
        #pragma unroll
        for (int i = 0; i < 8; ++i) {
            int arr = i >> 1;
            int idx = ((i & 1) << 8) + t;
            int row = idx >> 3, kg = (idx & 7) * 8;
            CP16(stg + arr * D_ARR + (uint32_t)row * 144 + kg * 2,
                 srcF[arr] + (size_t)row * LH + k0 + kg);
        }
        CP_COMMIT();
    };
    auto convert = [&](uint32_t uvb) {
        #pragma unroll
        for (int ps = 0; ps < 4; ++ps) {
            int l = ql + ps * 16;
            uint32_t ad = uvb + (uint32_t)l * 144 + (t & 15) * 8;
            float4 a = ra[ps], bb = rb[ps];
            float uv[2][4] = {{a.x + bb.x, a.y + bb.y, a.z + bb.z, a.w + bb.w},
                              {a.x - bb.x, a.y - bb.y, a.z - bb.z, a.w - bb.w}};
            #pragma unroll
            for (int s = 0; s < 2; ++s) {
                union { uint32_t u[2]; __nv_bfloat16 x[4]; } H, L;
                #pragma unroll
                for (int j = 0; j < 4; ++j) {
                    __nv_bfloat16 hi, lo;
                    split_bf16(uv[s][j], hi, lo);
                    H.x[j] = hi;  L.x[j] = lo;
                }
                *(uint2*)(smd + (ad - sb) + s * 2 * D_ARR)         = make_uint2(H.u[0], H.u[1]);
                *(uint2*)(smd + (ad - sb) + s * 2 * D_ARR + D_ARR) = make_uint2(L.u[0], L.u[1]);
            }
        }
    };

    const uint32_t aoff = (uint32_t)(wr * 16 + (lane & 15)) * 144 + (lane >> 4) * 16;
    const uint32_t boff = (uint32_t)(lane & 15) * 144 + (lane >> 4) * 16;

    float acc[8][4];
    #pragma unroll
    for (int i = 0; i < 8; ++i)
        #pragma unroll
        for (int j = 0; j < 4; ++j) acc[i][j] = 0.f;

    LDGQ(0);
    issueF(0, sb);
    for (int c = 0; c < 32; ++c) {
        const uint32_t uvb = sb + 2 * F_STG + (uint32_t)(c & 1) * F_STG;
        convert(uvb);
        if (c < 31) {
            LDGQ((c + 1) * 64);
            issueF(c + 1, sb + (uint32_t)((c + 1) & 1) * F_STG);
            CP_WAIT1();
        } else CP_WAIT0();
        __syncthreads();
        const uint32_t fst = sb + (uint32_t)(c & 1) * F_STG;
        const uint32_t aHi = fst + grp * (2 * D_ARR) + aoff, aLo = aHi + D_ARR;
        const uint32_t bHi = uvb + grp * (2 * D_ARR) + boff, bLo = bHi + D_ARR;
        #pragma unroll
        for (int ks = 0; ks < 4; ++ks) {
            uint32_t ah[4], al[4];
            ldsm4(ah, aHi + ks * 32);
            ldsm4(al, aLo + ks * 32);
            #pragma unroll
            for (int j = 0; j < 4; ++j) {
                uint32_t bh_[4], bl_[4];
                ldsm4t(bh_, bHi + ks * 2304 + j * 32);
                ldsm4t(bl_, bLo + ks * 2304 + j * 32);
                mma16816(acc[2 * j],     ah, bh_);
                mma16816(acc[2 * j],     ah, bl_);
                mma16816(acc[2 * j],     al, bh_);
                mma16816(acc[2 * j + 1], ah, bh_ + 2);
                mma16816(acc[2 * j + 1], ah, bl_ + 2);
                mma16816(acc[2 * j + 1], al, bh_ + 2);
            }
        }
        __syncthreads();
    }

    const int g = lane >> 2, q4 = lane & 3;
    float* xb = g_X + (size_t)bh * 8192;
    const int r0 = wr * 16 + g, r1 = r0 + 8;
    const int f2a = 2 * r0 - (r0 & 1) + 2 * grp;
    const int f2b = 2 * r1 - (r1 & 1) + 2 * grp;
    #pragma unroll
    for (int j = 0; j < 8; ++j) {
        int e0 = j * 8 + q4 * 2;
        xb[e0 * 128 + f2a]       = acc[j][0];
        xb[(e0 + 1) * 128 + f2a] = acc[j][1];
        xb[e0 * 128 + f2b]       = acc[j][2];
        xb[(e0 + 1) * 128 + f2b] = acc[j][3];
    }
}

// ---------------------------------------------------------------- Stage 2: mix
#define MIX_SMEM 98304       // Ws_r 32K | Ws_i 32K | Xs 32K
__global__ __launch_bounds__(256) void mix_kernel(const float* __restrict__ wr,
                                                  const float* __restrict__ wi) {
    extern __shared__ char sm[];
    float* Ws_r = (float*)sm;
    float* Ws_i = (float*)(sm + 32768);
    float* Xs   = (float*)(sm + 65536);
    const int h = blockIdx.x & 7, og = (blockIdx.x >> 3) & 7, bq = blockIdx.x >> 6;
    const int t = threadIdx.x;
    const int f2 = t & 31, ol = t >> 5;

    float acc[4][4];
    #pragma unroll
    for (int i = 0; i < 4; ++i)
        #pragma unroll
        for (int j = 0; j < 4; ++j) acc[i][j] = 0.f;

    for (int e0 = 0; e0 < 64; e0 += 16) {
        __syncthreads();
        #pragma unroll
        for (int i = 0; i < 8; ++i) {
            int c = t + i * 256;
            int row = c >> 4, m4 = (c & 15) * 4;
            int e = row >> 3, o = row & 7;
            size_t g = (((size_t)h * 64 + e0 + e) * 64 + og * 8 + o) * 64 + m4;
            *(float4*)&Ws_r[(e * 8 + o) * 64 + m4] = *(const float4*)&wr[g];
            *(float4*)&Ws_i[(e * 8 + o) * 64 + m4] = *(const float4*)&wi[g];
        }
        #pragma unroll
        for (int i = 0; i < 8; ++i) {
            int c = t + i * 256;
            int row = c >> 5, f4 = (c & 31) * 4;
            int b = row >> 4, e = row & 15;
            int bh = (bq * 4 + b) * 8 + h;
            *(float4*)&Xs[(b * 16 + e) * 128 + f4] =
                *(const float4*)&g_X[(size_t)bh * 8192 + (e0 + e) * 128 + f4];
        }
        __syncthreads();
        #pragma unroll 4
        for (int e = 0; e < 16; ++e) {
            float2 w_r = *(float2*)&Ws_r[(e * 8 + ol) * 64 + 2 * f2];
            float2 w_i = *(float2*)&Ws_i[(e * 8 + ol) * 64 + 2 * f2];
            #pragma unroll
            for (int b = 0; b < 4; ++b) {
                float4 x = *(float4*)&Xs[(b * 16 + e) * 128 + 4 * f2];
                acc[b][0] += x.x * w_r.x - x.y * w_i.x;
                acc[b][1] += x.x * w_i.x + x.y * w_r.x;
                acc[b][2] += x.z * w_r.y - x.w * w_i.y;
                acc[b][3] += x.z * w_i.y + x.w * w_r.y;
            }
        }
    }
    const float a0 = (f2 == 0) ? (1.0f / 4096.0f) : (2.0f / 4096.0f);
    const float a1 = 2.0f / 4096.0f;
    #pragma unroll
    for (int b = 0; b < 4; ++b) {
        size_t row = (size_t)((bq * 4 + b) * 8 + h) * 64 + og * 8 + ol;
        float ve0 = a0 * acc[b][0], ve1 = -a0 * acc[b][1];
        float vo0 = a1 * acc[b][2], vo1 = -a1 * acc[b][3];
        union { uint32_t u; __nv_bfloat16 x[2]; } p;
        __nv_bfloat16 hi, lo, hi2, lo2;
        split_bf16(ve0, hi, lo);  split_bf16(ve1, hi2, lo2);
        p.x[0] = hi;  p.x[1] = hi2;  *(uint32_t*)&g_Ce_hi[row * 64 + 2 * f2] = p.u;
        p.x[0] = lo;  p.x[1] = lo2;  *(uint32_t*)&g_Ce_lo[row * 64 + 2 * f2] = p.u;
        split_bf16(vo0, hi, lo);  split_bf16(vo1, hi2, lo2);
        p.x[0] = hi;  p.x[1] = hi2;  *(uint32_t*)&g_Co_hi[row * 64 + 2 * f2] = p.u;
        p.x[0] = lo;  p.x[1] = lo2;  *(uint32_t*)&g_Co_lo[row * 64 + 2 * f2] = p.u;
    }
}

// ---------------------------------------------------------------- Stage 3: iDFT
// CTA = (bh, lq). smem 110.6KB -> 2 CTAs/SM (launch_bounds(256,2)).
// Warps 0-3: E GEMM, 4-7: O GEMM over 64-l chunks, G double-buffered.
// Combine via fp32 staging in the consumed G stage -> coalesced float4 stores.
#define IJ_ARR 9216                  // 64 rows * 144B
#define IA_SZ  (4 * IJ_ARR)          // 36864 (Ce_hi|Ce_lo|Co_hi|Co_lo)
#define IG_SZ  (4 * IJ_ARR)          // 36864 per G stage
#define IDFT_SMEM (IA_SZ + 2 * IG_SZ)   // 110592
#define EPAD 68                      // staging row stride (floats)

__global__ __launch_bounds__(256, 2) void idft_mma_kernel(float* __restrict__ out) {
    extern __shared__ char smi[];
    const uint32_t sb = smem_u32(smi);
    const int bh = blockIdx.x & 127, lq = blockIdx.x >> 7;   // lq 0..3
    const int t = threadIdx.x, w = t >> 5, lane = t & 31;
    const int grp = w >> 2, w4 = w & 3;
    const size_t pC = (size_t)bh * 64 * 64;

    const __nv_bfloat16* srcA[4] = { g_Ce_hi + pC, g_Ce_lo + pC, g_Co_hi + pC, g_Co_lo + pC };
    const __nv_bfloat16* srcG[4] = { g_Gte_hi, g_Gte_lo, g_Gto_hi, g_Gto_lo };

    auto issueG = [&](int lc, uint32_t stg) {     // G chunk: 64 l rows x 64 k, 4 arrays
        const size_t lG = (size_t)lc * 64 * 64;
        #pragma unroll
        for (int i = 0; i < 8; ++i) {
            int arr = i >> 1;
            int idx = ((i & 1) << 8) + t;
            int row = idx >> 3, kg = (idx & 7) * 8;
            CP16(stg + arr * IJ_ARR + (uint32_t)row * 144 + kg * 2,
                 srcG[arr] + lG + (size_t)row * 64 + kg);
        }
    };

    // A once + G(lq*8), one group
    #pragma unroll
    for (int i = 0; i < 8; ++i) {
        int arr = i >> 1;
        int idx = ((i & 1) << 8) + t;
        int row = idx >> 3, kg = (idx & 7) * 8;
        CP16(sb + arr * IJ_ARR + (uint32_t)row * 144 + kg * 2,
             srcA[arr] + (size_t)row * 64 + kg);
    }
    issueG(lq * 8, sb + IA_SZ);
    CP_COMMIT();

    const uint32_t aoff = (uint32_t)(w4 * 16 + (lane & 15)) * 144 + (lane >> 4) * 16;
    const uint32_t boff = (uint32_t)((lane >> 4) * 8 + (lane & 7)) * 144 + ((lane >> 3) & 1) * 16;
    const int g = lane >> 2, q4 = lane & 3;
    const int crow = t >> 4, ccol = (t & 15) * 4;   // combine-pass mapping

    for (int cc = 0; cc < 8; ++cc) {
        const int lc = lq * 8 + cc;
        const uint32_t gst = sb + IA_SZ + (uint32_t)(cc & 1) * IG_SZ;
        if (cc < 7) {
            issueG(lc + 1, sb + IA_SZ + (uint32_t)((cc + 1) & 1) * IG_SZ);
            CP_COMMIT();
            CP_WAIT1();
        } else CP_WAIT0();
        __syncthreads();

        float acc[8][4];
        #pragma unroll
        for (int i = 0; i < 8; ++i)
            #pragma unroll
            for (int j = 0; j < 4; ++j) acc[i][j] = 0.f;

        const uint32_t aHi = sb + grp * (2 * IJ_ARR) + aoff, aLo = aHi + IJ_ARR;
        const uint32_t bHi = gst + grp * (2 * IJ_ARR) + boff, bLo = bHi + IJ_ARR;
        #pragma unroll
        for (int ks = 0; ks < 4; ++ks) {
            uint32_t ah[4], al[4];
            ldsm4(ah, aHi + ks * 32);
            ldsm4(al, aLo + ks * 32);
            #pragma unroll
            for (int j = 0; j < 4; ++j) {
                uint32_t bh_[4], bl_[4];
                ldsm4(bh_, bHi + j * 2304 + ks * 32);    // 2304 = 16*144
                ldsm4(bl_, bLo + j * 2304 + ks * 32);
                mma16816(acc[2 * j],     ah, bh_);
                mma16816(acc[2 * j],     ah, bl_);
                mma16816(acc[2 * j],     al, bh_);
                mma16816(acc[2 * j + 1], ah, bh_ + 2);
                mma16816(acc[2 * j + 1], ah, bl_ + 2);
                mma16816(acc[2 * j + 1], al, bh_ + 2);
            }
        }
        __syncthreads();       // all warps done reading stage gst

        // stage accs fp32 into consumed G stage: E at +0, O at +17408B
        float* stgf = (float*)(smi + (gst - sb) + grp * 17408);
        const int r0 = w4 * 16 + g, r1 = r0 + 8;
        #pragma unroll
        for (int j = 0; j < 8; ++j) {
            int col = j * 8 + q4 * 2;
            *(float2*)&stgf[r0 * EPAD + col] = make_float2(acc[j][0], acc[j][1]);
            *(float2*)&stgf[r1 * EPAD + col] = make_float2(acc[j][2], acc[j][3]);
        }
        __syncthreads();

        // combine + coalesced store: 64 rows x 64 cols, 4 rows/thread-pass
        float* Ebuf = (float*)(smi + (gst - sb));
        float* Obuf = Ebuf + 4352;   // 17408 bytes
        #pragma unroll
        for (int i = 0; i < 4; ++i) {
            int r = crow + 16 * i;
            float4 E = *(float4*)&Ebuf[r * EPAD + ccol];
            float4 O = *(float4*)&Obuf[r * EPAD + ccol];
            float* op = out + ((size_t)bh * 64 + r) * LSEQ + lc * 64 + ccol;
            *(float4*)op = make_float4(E.x + O.x, E.y + O.y, E.z + O.z, E.w + O.w);
            *(float4*)(op + LH) = make_float4(E.x - O.x, E.y - O.y, E.z - O.z, E.w - O.w);
        }
        __syncthreads();       // protect stage before next cp.async reuse
    }
}

// ---------------------------------------------------------------------------
extern "C" void kernel_launch(void* const* d_in, const int* in_sizes, int n_in,
                              void* d_out, int out_size) {
    const float* q = (const float*)d_in[0];
    const float* wr = nullptr;
    const float* wi = nullptr;
    for (int i = 0; i < n_in; ++i) {
        if (in_sizes[i] == 8 * 64 * 64 * 64) {
            if (!wr) wr = (const float*)d_in[i];
            else if (!wi) wi = (const float*)d_in[i];
        }
    }
    float* out = (float*)d_out;

    cudaFuncSetAttribute(dft_fused_kernel, cudaFuncAttributeMaxDynamicSharedMemorySize, DFT_SMEM);
    cudaFuncSetAttribute(mix_kernel,       cudaFuncAttributeMaxDynamicSharedMemorySize, MIX_SMEM);
    cudaFuncSetAttribute(idft_mma_kernel,  cudaFuncAttributeMaxDynamicSharedMemorySize, IDFT_SMEM);

    init_basis_kernel<<<512, 256>>>();
    dft_fused_kernel<<<NBH, 256, DFT_SMEM>>>(q);
    mix_kernel<<<256, 256, MIX_SMEM>>>(wr, wi);
    idft_mma_kernel<<<512, 256, IDFT_SMEM>>>(out);
}

// round 11
// speedup vs baseline: 1.2124x; 1.1039x over previous
#include <cuda_runtime.h>
#include <cuda_fp16.h>
#include <cstdint>
#include <cstddef>

#define LSEQ 4096
#define LH   2048
#define NBH  128
#define CSCALE 65536.0f
#define CINV  (1.0f / 65536.0f)

// ------------------------------------------------------------- gmem scratch
__device__ __half g_Fu_hi[64 * LH], g_Fu_lo[64 * LH];   // fwd basis even-f rows
__device__ __half g_Fv_hi[64 * LH], g_Fv_lo[64 * LH];   // fwd basis odd-f rows
__device__ __half g_Gte_hi[LH * 64], g_Gte_lo[LH * 64]; // inv basis even parity
__device__ __half g_Gto_hi[LH * 64], g_Gto_lo[LH * 64]; // inv basis odd parity
__device__ float  g_X[NBH * 64 * 128];                  // [bh][e][f2]
__device__ __half g_Ce[NBH * 64 * 64], g_Co[NBH * 64 * 64];   // C * 2^16

// ------------------------------------------------------------- helpers
__device__ __forceinline__ uint32_t smem_u32(const void* p) {
    uint32_t a;
    asm("{ .reg .u64 t; cvta.to.shared.u64 t, %1; cvt.u32.u64 %0, t; }" : "=r"(a) : "l"(p));
    return a;
}
__device__ __forceinline__ void split_fp16(float x, __half& hi, __half& lo) {
    hi = __float2half(x);
    lo = __float2half(x - __half2float(hi));
}
__device__ __forceinline__ void ldsm4(uint32_t* r, uint32_t addr) {
    asm volatile("ldmatrix.sync.aligned.m8n8.x4.shared.b16 {%0,%1,%2,%3}, [%4];"
                 : "=r"(r[0]), "=r"(r[1]), "=r"(r[2]), "=r"(r[3]) : "r"(addr));
}
__device__ __forceinline__ void ldsm4t(uint32_t* r, uint32_t addr) {
    asm volatile("ldmatrix.sync.aligned.m8n8.x4.trans.shared.b16 {%0,%1,%2,%3}, [%4];"
                 : "=r"(r[0]), "=r"(r[1]), "=r"(r[2]), "=r"(r[3]) : "r"(addr));
}
__device__ __forceinline__ void mma16816(float* d, const uint32_t* a, const uint32_t* b) {
    asm volatile("mma.sync.aligned.m16n8k16.row.col.f32.f16.f16.f32 "
                 "{%0,%1,%2,%3}, {%4,%5,%6,%7}, {%8,%9}, {%0,%1,%2,%3};"
                 : "+f"(d[0]), "+f"(d[1]), "+f"(d[2]), "+f"(d[3])
                 : "r"(a[0]), "r"(a[1]), "r"(a[2]), "r"(a[3]), "r"(b[0]), "r"(b[1]));
}
#define CP16(sa, gp) asm volatile("cp.async.cg.shared.global [%0], [%1], 16;" \
                                  :: "r"((uint32_t)(sa)), "l"(gp) : "memory")
#define CP_COMMIT()  asm volatile("cp.async.commit_group;" ::: "memory")
#define CP_WAIT0()   asm volatile("cp.async.wait_group 0;" ::: "memory")
#define CP_WAIT1()   asm volatile("cp.async.wait_group 1;" ::: "memory")

// ---------------------------------------------------------------- basis init
__global__ void init_basis_kernel() {
    int idx = blockIdx.x * 256 + threadIdx.x;      // < 131072
    {   // Fu/Fv rows ru = 2*fe + c (c=0 cos, c=1 -sin), half domain
        int ru = idx >> 11, l = idx & 2047;
        int fe = ru >> 1, c = ru & 1;
        float s, cs;
        __half hi, lo;
        sincospif((float)((l * (2 * fe)) & 4095) / 2048.0f, &s, &cs);
        split_fp16(c ? -s : cs, hi, lo);
        g_Fu_hi[ru * LH + l] = hi;  g_Fu_lo[ru * LH + l] = lo;
        sincospif((float)((l * (2 * fe + 1)) & 4095) / 2048.0f, &s, &cs);
        split_fp16(c ? -s : cs, hi, lo);
        g_Fv_hi[ru * LH + l] = hi;  g_Fv_lo[ru * LH + l] = lo;
    }
    {   // Gte/Gto: [l][kk=2*fe+c], c=0 cos, c=1 +sin
        int l = idx >> 6, kk = idx & 63;
        int fe = kk >> 1, c = kk & 1;
        float s, cs;
        __half hi, lo;
        sincospif((float)((l * (2 * fe)) & 4095) / 2048.0f, &s, &cs);
        split_fp16(c ? s : cs, hi, lo);
        g_Gte_hi[l * 64 + kk] = hi;  g_Gte_lo[l * 64 + kk] = lo;
        sincospif((float)((l * (2 * fe + 1)) & 4095) / 2048.0f, &s, &cs);
        split_fp16(c ? s : cs, hi, lo);
        g_Gto_hi[l * 64 + kk] = hi;  g_Gto_lo[l * 64 + kk] = lo;
    }
}

// ---------------------------------------------------------------- Stage 1: DFT
// Fused q->butterfly->fp16->HMMA. Basis split hi/lo (2 passes); u/v single fp16.
#define D_ARR  9216                  // 64 rows * 144B
#define F_STG  (4 * D_ARR)           // Fu_hi|Fu_lo|Fv_hi|Fv_lo = 36864
#define UV_STG (2 * D_ARR)           // u|v = 18432
#define DFT_SMEM (2 * F_STG + 2 * UV_STG)   // 110592

__global__ __launch_bounds__(256) void dft_fused_kernel(const float* __restrict__ q) {
    extern __shared__ char smd[];
    const uint32_t sb = smem_u32(smd);
    const int bh = blockIdx.x, b = bh >> 3, h = bh & 7;
    const int t = threadIdx.x, w = t >> 5, lane = t & 31;
    const int grp = w >> 2, wr = w & 3;
    const float* qb = q + ((size_t)b * LSEQ * 8 + h) * 64;

    const __half* srcF[4] = { g_Fu_hi, g_Fu_lo, g_Fv_hi, g_Fv_lo };

    const int ql = t >> 4, qe4 = (t & 15) * 4;
    float4 ra[4], rb[4];
    auto LDGQ = [&](int l0) {
        #pragma unroll
        for (int ps = 0; ps < 4; ++ps) {
            const float* p = qb + (size_t)(l0 + ql + ps * 16) * 512 + qe4;
            ra[ps] = *(const float4*)p;
            rb[ps] = *(const float4*)(p + (size_t)LH * 512);
        }
    };
    auto issueF = [&](int c, uint32_t stg) {
        const size_t k0 = (size_t)c * 64;
        #pragma unroll
        for (int i = 0; i < 8; ++i) {
            int arr = i >> 1;
            int idx = ((i & 1) << 8) + t;
            int row = idx >> 3, kg = (idx & 7) * 8;
            CP16(stg + arr * D_ARR + (uint32_t)row * 144 + kg * 2,
                 srcF[arr] + (size_t)row * LH + k0 + kg);
        }
        CP_COMMIT();
    };
    auto convert = [&](uint32_t uvoff) {          // u at +0, v at +D_ARR; [l][e]
        #pragma unroll
        for (int ps = 0; ps < 4; ++ps) {
            int l = ql + ps * 16;
            uint32_t ad = uvoff + (uint32_t)l * 144 + (t & 15) * 8;
            float4 a = ra[ps], bb = rb[ps];
            union { uint2 v; __half x[4]; } U, V;
            U.x[0] = __float2half(a.x + bb.x);  V.x[0] = __float2half(a.x - bb.x);
            U.x[1] = __float2half(a.y + bb.y);  V.x[1] = __float2half(a.y - bb.y);
            U.x[2] = __float2half(a.z + bb.z);  V.x[2] = __float2half(a.z - bb.z);
            U.x[3] = __float2half(a.w + bb.w);  V.x[3] = __float2half(a.w - bb.w);
            *(uint2*)(smd + ad)         = U.v;
            *(uint2*)(smd + ad + D_ARR) = V.v;
        }
    };

    const uint32_t aoff = (uint32_t)(wr * 16 + (lane & 15)) * 144 + (lane >> 4) * 16;
    const uint32_t boff = (uint32_t)(lane & 15) * 144 + (lane >> 4) * 16;

    float acc[8][4];
    #pragma unroll
    for (int i = 0; i < 8; ++i)
        #pragma unroll
        for (int j = 0; j < 4; ++j) acc[i][j] = 0.f;

    LDGQ(0);
    issueF(0, sb);
    for (int c = 0; c < 32; ++c) {
        const uint32_t uvoff = 2 * F_STG + (uint32_t)(c & 1) * UV_STG;
        convert(uvoff);
        if (c < 31) {
            LDGQ((c + 1) * 64);
            issueF(c + 1, sb + (uint32_t)((c + 1) & 1) * F_STG);
            CP_WAIT1();
        } else CP_WAIT0();
        __syncthreads();
        const uint32_t fst = sb + (uint32_t)(c & 1) * F_STG;
        const uint32_t aHi = fst + grp * (2 * D_ARR) + aoff, aLo = aHi + D_ARR;
        const uint32_t bB  = sb + uvoff + grp * D_ARR + boff;
        #pragma unroll
        for (int ks = 0; ks < 4; ++ks) {
            uint32_t ah[4], al[4];
            ldsm4(ah, aHi + ks * 32);
            ldsm4(al, aLo + ks * 32);
            #pragma unroll
            for (int j = 0; j < 4; ++j) {
                uint32_t bv[4];
                ldsm4t(bv, bB + ks * 2304 + j * 32);    // 2304 = 16*144
                mma16816(acc[2 * j],     ah, bv);
                mma16816(acc[2 * j],     al, bv);
                mma16816(acc[2 * j + 1], ah, bv + 2);
                mma16816(acc[2 * j + 1], al, bv + 2);
            }
        }
        __syncthreads();
    }

    const int g = lane >> 2, q4 = lane & 3;
    float* xb = g_X + (size_t)bh * 8192;
    const int r0 = wr * 16 + g, r1 = r0 + 8;
    const int f2a = 2 * r0 - (r0 & 1) + 2 * grp;
    const int f2b = 2 * r1 - (r1 & 1) + 2 * grp;
    #pragma unroll
    for (int j = 0; j < 8; ++j) {
        int e0 = j * 8 + q4 * 2;
        xb[e0 * 128 + f2a]       = acc[j][0];
        xb[(e0 + 1) * 128 + f2a] = acc[j][1];
        xb[e0 * 128 + f2b]       = acc[j][2];
        xb[(e0 + 1) * 128 + f2b] = acc[j][3];
    }
}

// ---------------------------------------------------------------- Stage 2: mix
#define MIX_SMEM 98304       // Ws_r 32K | Ws_i 32K | Xs 32K
__global__ __launch_bounds__(256) void mix_kernel(const float* __restrict__ wr,
                                                  const float* __restrict__ wi) {
    extern __shared__ char sm[];
    float* Ws_r = (float*)sm;
    float* Ws_i = (float*)(sm + 32768);
    float* Xs   = (float*)(sm + 65536);
    const int h = blockIdx.x & 7, og = (blockIdx.x >> 3) & 7, bq = blockIdx.x >> 6;
    const int t = threadIdx.x;
    const int f2 = t & 31, ol = t >> 5;

    float acc[4][4];
    #pragma unroll
    for (int i = 0; i < 4; ++i)
        #pragma unroll
        for (int j = 0; j < 4; ++j) acc[i][j] = 0.f;

    for (int e0 = 0; e0 < 64; e0 += 16) {
        __syncthreads();
        #pragma unroll
        for (int i = 0; i < 8; ++i) {
            int c = t + i * 256;
            int row = c >> 4, m4 = (c & 15) * 4;
            int e = row >> 3, o = row & 7;
            size_t g = (((size_t)h * 64 + e0 + e) * 64 + og * 8 + o) * 64 + m4;
            *(float4*)&Ws_r[(e * 8 + o) * 64 + m4] = *(const float4*)&wr[g];
            *(float4*)&Ws_i[(e * 8 + o) * 64 + m4] = *(const float4*)&wi[g];
        }
        #pragma unroll
        for (int i = 0; i < 8; ++i) {
            int c = t + i * 256;
            int row = c >> 5, f4 = (c & 31) * 4;
            int b = row >> 4, e = row & 15;
            int bh = (bq * 4 + b) * 8 + h;
            *(float4*)&Xs[(b * 16 + e) * 128 + f4] =
                *(const float4*)&g_X[(size_t)bh * 8192 + (e0 + e) * 128 + f4];
        }
        __syncthreads();
        #pragma unroll 4
        for (int e = 0; e < 16; ++e) {
            float2 w_r = *(float2*)&Ws_r[(e * 8 + ol) * 64 + 2 * f2];
            float2 w_i = *(float2*)&Ws_i[(e * 8 + ol) * 64 + 2 * f2];
            #pragma unroll
            for (int b = 0; b < 4; ++b) {
                float4 x = *(float4*)&Xs[(b * 16 + e) * 128 + 4 * f2];
                acc[b][0] += x.x * w_r.x - x.y * w_i.x;
                acc[b][1] += x.x * w_i.x + x.y * w_r.x;
                acc[b][2] += x.z * w_r.y - x.w * w_i.y;
                acc[b][3] += x.z * w_i.y + x.w * w_r.y;
            }
        }
    }
    const float a0 = ((f2 == 0) ? (1.0f / 4096.0f) : (2.0f / 4096.0f)) * CSCALE;
    const float a1 = (2.0f / 4096.0f) * CSCALE;
    #pragma unroll
    for (int b = 0; b < 4; ++b) {
        size_t row = (size_t)((bq * 4 + b) * 8 + h) * 64 + og * 8 + ol;
        union { uint32_t u; __half x[2]; } p;
        p.x[0] = __float2half(a0 * acc[b][0]);
        p.x[1] = __float2half(-a0 * acc[b][1]);
        *(uint32_t*)&g_Ce[row * 64 + 2 * f2] = p.u;
        p.x[0] = __float2half(a1 * acc[b][2]);
        p.x[1] = __float2half(-a1 * acc[b][3]);
        *(uint32_t*)&g_Co[row * 64 + 2 * f2] = p.u;
    }
}

// ---------------------------------------------------------------- Stage 3: iDFT
// CTA = (bh, lq). C single fp16 (scaled), G split hi/lo -> 2 passes.
// smem 92KB -> 2 CTAs/SM. Warps 0-3: E, 4-7: O; staged fp32 combine (x 2^-16).
#define IJ_ARR 9216                  // 64 rows * 144B
#define IA_SZ  (2 * IJ_ARR)          // Ce|Co = 18432
#define IG_SZ  (4 * IJ_ARR)          // Gte_hi|Gte_lo|Gto_hi|Gto_lo = 36864/stage
#define IDFT_SMEM (IA_SZ + 2 * IG_SZ)   // 92160
#define EPAD 68

__global__ __launch_bounds__(256, 2) void idft_mma_kernel(float* __restrict__ out) {
    extern __shared__ char smi[];
    const uint32_t sb = smem_u32(smi);
    const int bh = blockIdx.x & 127, lq = blockIdx.x >> 7;   // lq 0..3
    const int t = threadIdx.x, w = t >> 5, lane = t & 31;
    const int grp = w >> 2, w4 = w & 3;
    const size_t pC = (size_t)bh * 64 * 64;

    const __half* srcA[2] = { g_Ce + pC, g_Co + pC };
    const __half* srcG[4] = { g_Gte_hi, g_Gte_lo, g_Gto_hi, g_Gto_lo };

    auto issueG = [&](int lc, uint32_t stg) {     // 64 l rows x 64 k, 4 arrays
        const size_t lG = (size_t)lc * 64 * 64;
        #pragma unroll
        for (int i = 0; i < 8; ++i) {
            int arr = i >> 1;
            int idx = ((i & 1) << 8) + t;
            int row = idx >> 3, kg = (idx & 7) * 8;
            CP16(stg + arr * IJ_ARR + (uint32_t)row * 144 + kg * 2,
                 srcG[arr] + lG + (size_t)row * 64 + kg);
        }
    };

    // A once (2 arrays) + G(lq*8), one group
    #pragma unroll
    for (int i = 0; i < 4; ++i) {
        int arr = i >> 1;
        int idx = ((i & 1) << 8) + t;
        int row = idx >> 3, kg = (idx & 7) * 8;
        CP16(sb + arr * IJ_ARR + (uint32_t)row * 144 + kg * 2,
             srcA[arr] + (size_t)row * 64 + kg);
    }
    issueG(lq * 8, sb + IA_SZ);
    CP_COMMIT();

    const uint32_t aoff = (uint32_t)(w4 * 16 + (lane & 15)) * 144 + (lane >> 4) * 16;
    const uint32_t boff = (uint32_t)((lane >> 4) * 8 + (lane & 7)) * 144 + ((lane >> 3) & 1) * 16;
    const int g = lane >> 2, q4 = lane & 3;
    const int crow = t >> 4, ccol = (t & 15) * 4;

    for (int cc = 0; cc < 8; ++cc) {
        const int lc = lq * 8 + cc;
        const uint32_t gst = sb + IA_SZ + (uint32_t)(cc & 1) * IG_SZ;
        if (cc < 7) {
            issueG(lc + 1, sb + IA_SZ + (uint32_t)((cc + 1) & 1) * IG_SZ);
            CP_COMMIT();
            CP_WAIT1();
        } else CP_WAIT0();
        __syncthreads();

        float acc[8][4];
        #pragma unroll
        for (int i = 0; i < 8; ++i)
            #pragma unroll
            for (int j = 0; j < 4; ++j) acc[i][j] = 0.f;

        const uint32_t aC  = sb + grp * IJ_ARR + aoff;
        const uint32_t bHi = gst + grp * (2 * IJ_ARR) + boff, bLo = bHi + IJ_ARR;
        #pragma unroll
        for (int ks = 0; ks < 4; ++ks) {
            uint32_t ac[4];
            ldsm4(ac, aC + ks * 32);
            #pragma unroll
            for (int j = 0; j < 4; ++j) {
                uint32_t bh_[4], bl_[4];
                ldsm4(bh_, bHi + j * 2304 + ks * 32);
                ldsm4(bl_, bLo + j * 2304 + ks * 32);
                mma16816(acc[2 * j],     ac, bh_);
                mma16816(acc[2 * j],     ac, bl_);
                mma16816(acc[2 * j + 1], ac, bh_ + 2);
                mma16816(acc[2 * j + 1], ac, bl_ + 2);
            }
        }
        __syncthreads();       // all warps done reading stage gst

        // stage accs fp32 into consumed G stage: E at +0, O at +17408B
        float* stgf = (float*)(smi + (gst - sb) + grp * 17408);
        const int r0 = w4 * 16 + g, r1 = r0 + 8;
        #pragma unroll
        for (int j = 0; j < 8; ++j) {
            int col = j * 8 + q4 * 2;
            *(float2*)&stgf[r0 * EPAD + col] = make_float2(acc[j][0], acc[j][1]);
            *(float2*)&stgf[r1 * EPAD + col] = make_float2(acc[j][2], acc[j][3]);
        }
        __syncthreads();

        // combine (unscale 2^-16) + coalesced store
        float* Ebuf = (float*)(smi + (gst - sb));
        float* Obuf = Ebuf + 4352;   // 17408 bytes
        #pragma unroll
        for (int i = 0; i < 4; ++i) {
            int r = crow + 16 * i;
            float4 E = *(float4*)&Ebuf[r * EPAD + ccol];
            float4 O = *(float4*)&Obuf[r * EPAD + ccol];
            float* op = out + ((size_t)bh * 64 + r) * LSEQ + lc * 64 + ccol;
            *(float4*)op = make_float4((E.x + O.x) * CINV, (E.y + O.y) * CINV,
                                       (E.z + O.z) * CINV, (E.w + O.w) * CINV);
            *(float4*)(op + LH) = make_float4((E.x - O.x) * CINV, (E.y - O.y) * CINV,
                                              (E.z - O.z) * CINV, (E.w - O.w) * CINV);
        }
        __syncthreads();
    }
}

// ---------------------------------------------------------------------------
extern "C" void kernel_launch(void* const* d_in, const int* in_sizes, int n_in,
                              void* d_out, int out_size) {
    const float* q = (const float*)d_in[0];
    const float* wr = nullptr;
    const float* wi = nullptr;
    for (int i = 0; i < n_in; ++i) {
        if (in_sizes[i] == 8 * 64 * 64 * 64) {
            if (!wr) wr = (const float*)d_in[i];
            else if (!wi) wi = (const float*)d_in[i];
        }
    }
    float* out = (float*)d_out;

    cudaFuncSetAttribute(dft_fused_kernel, cudaFuncAttributeMaxDynamicSharedMemorySize, DFT_SMEM);
    cudaFuncSetAttribute(mix_kernel,       cudaFuncAttributeMaxDynamicSharedMemorySize, MIX_SMEM);
    cudaFuncSetAttribute(idft_mma_kernel,  cudaFuncAttributeMaxDynamicSharedMemorySize, IDFT_SMEM);

    init_basis_kernel<<<512, 256>>>();
    dft_fused_kernel<<<NBH, 256, DFT_SMEM>>>(q);
    mix_kernel<<<256, 256, MIX_SMEM>>>(wr, wi);
    idft_mma_kernel<<<512, 256, IDFT_SMEM>>>(out);
}

// round 12
// speedup vs baseline: 1.2690x; 1.0467x over previous
#include <cuda_runtime.h>
#include <cuda_fp16.h>
#include <cstdint>
#include <cstddef>

#define LSEQ 4096
#define LH   2048
#define NBH  128
#define CSCALE 65536.0f
#define CINV  (1.0f / 65536.0f)

// ------------------------------------------------------------- gmem scratch
__device__ __half g_Fu_hi[64 * LH], g_Fu_lo[64 * LH];   // fwd basis even-f rows
__device__ __half g_Fv_hi[64 * LH], g_Fv_lo[64 * LH];   // fwd basis odd-f rows
__device__ __half g_Gte_hi[LH * 64], g_Gte_lo[LH * 64]; // inv basis even parity
__device__ __half g_Gto_hi[LH * 64], g_Gto_lo[LH * 64]; // inv basis odd parity
__device__ float  g_X[NBH * 64 * 128];                  // [bh][e][f2]
__device__ __half g_Ce[NBH * 64 * 64], g_Co[NBH * 64 * 64];   // C * 2^16

// ------------------------------------------------------------- helpers
__device__ __forceinline__ uint32_t smem_u32(const void* p) {
    uint32_t a;
    asm("{ .reg .u64 t; cvta.to.shared.u64 t, %1; cvt.u32.u64 %0, t; }" : "=r"(a) : "l"(p));
    return a;
}
__device__ __forceinline__ void split_fp16(float x, __half& hi, __half& lo) {
    hi = __float2half(x);
    lo = __float2half(x - __half2float(hi));
}
__device__ __forceinline__ void ldsm4(uint32_t* r, uint32_t addr) {
    asm volatile("ldmatrix.sync.aligned.m8n8.x4.shared.b16 {%0,%1,%2,%3}, [%4];"
                 : "=r"(r[0]), "=r"(r[1]), "=r"(r[2]), "=r"(r[3]) : "r"(addr));
}
__device__ __forceinline__ void ldsm4t(uint32_t* r, uint32_t addr) {
    asm volatile("ldmatrix.sync.aligned.m8n8.x4.trans.shared.b16 {%0,%1,%2,%3}, [%4];"
                 : "=r"(r[0]), "=r"(r[1]), "=r"(r[2]), "=r"(r[3]) : "r"(addr));
}
__device__ __forceinline__ void mma16816(float* d, const uint32_t* a, const uint32_t* b) {
    asm volatile("mma.sync.aligned.m16n8k16.row.col.f32.f16.f16.f32 "
                 "{%0,%1,%2,%3}, {%4,%5,%6,%7}, {%8,%9}, {%0,%1,%2,%3};"
                 : "+f"(d[0]), "+f"(d[1]), "+f"(d[2]), "+f"(d[3])
                 : "r"(a[0]), "r"(a[1]), "r"(a[2]), "r"(a[3]), "r"(b[0]), "r"(b[1]));
}
#define CP16(sa, gp) asm volatile("cp.async.cg.shared.global [%0], [%1], 16;" \
                                  :: "r"((uint32_t)(sa)), "l"(gp) : "memory")
#define CP_COMMIT()  asm volatile("cp.async.commit_group;" ::: "memory")
#define CP_WAIT0()   asm volatile("cp.async.wait_group 0;" ::: "memory")
#define CP_WAIT1()   asm volatile("cp.async.wait_group 1;" ::: "memory")

// ---------------------------------------------------------------- basis init
__global__ void init_basis_kernel() {
    int idx = blockIdx.x * 256 + threadIdx.x;      // < 131072
    {   // Fu/Fv rows ru = 2*fe + c (c=0 cos, c=1 -sin), half domain
        int ru = idx >> 11, l = idx & 2047;
        int fe = ru >> 1, c = ru & 1;
        float s, cs;
        __half hi, lo;
        sincospif((float)((l * (2 * fe)) & 4095) / 2048.0f, &s, &cs);
        split_fp16(c ? -s : cs, hi, lo);
        g_Fu_hi[ru * LH + l] = hi;  g_Fu_lo[ru * LH + l] = lo;
        sincospif((float)((l * (2 * fe + 1)) & 4095) / 2048.0f, &s, &cs);
        split_fp16(c ? -s : cs, hi, lo);
        g_Fv_hi[ru * LH + l] = hi;  g_Fv_lo[ru * LH + l] = lo;
    }
    {   // Gte/Gto: [l][kk=2*fe+c], c=0 cos, c=1 +sin
        int l = idx >> 6, kk = idx & 63;
        int fe = kk >> 1, c = kk & 1;
        float s, cs;
        __half hi, lo;
        sincospif((float)((l * (2 * fe)) & 4095) / 2048.0f, &s, &cs);
        split_fp16(c ? s : cs, hi, lo);
        g_Gte_hi[l * 64 + kk] = hi;  g_Gte_lo[l * 64 + kk] = lo;
        sincospif((float)((l * (2 * fe + 1)) & 4095) / 2048.0f, &s, &cs);
        split_fp16(c ? s : cs, hi, lo);
        g_Gto_hi[l * 64 + kk] = hi;  g_Gto_lo[l * 64 + kk] = lo;
    }
}

// ---------------------------------------------------------------- Stage 1: DFT
// Fused q->butterfly->fp16->HMMA. Basis split hi/lo (2 passes); u/v single fp16.
#define D_ARR  9216                  // 64 rows * 144B
#define F_STG  (4 * D_ARR)           // Fu_hi|Fu_lo|Fv_hi|Fv_lo = 36864
#define UV_STG (2 * D_ARR)           // u|v = 18432
#define DFT_SMEM (2 * F_STG + 2 * UV_STG)   // 110592

__global__ __launch_bounds__(256) void dft_fused_kernel(const float* __restrict__ q) {
    extern __shared__ char smd[];
    const uint32_t sb = smem_u32(smd);
    const int bh = blockIdx.x, b = bh >> 3, h = bh & 7;
    const int t = threadIdx.x, w = t >> 5, lane = t & 31;
    const int grp = w >> 2, wr = w & 3;
    const float* qb = q + ((size_t)b * LSEQ * 8 + h) * 64;

    const __half* srcF[4] = { g_Fu_hi, g_Fu_lo, g_Fv_hi, g_Fv_lo };

    const int ql = t >> 4, qe4 = (t & 15) * 4;
    float4 ra[4], rb[4];
    auto LDGQ = [&](int l0) {
        #pragma unroll
        for (int ps = 0; ps < 4; ++ps) {
            const float* p = qb + (size_t)(l0 + ql + ps * 16) * 512 + qe4;
            ra[ps] = *(const float4*)p;
            rb[ps] = *(const float4*)(p + (size_t)LH * 512);
        }
    };
    auto issueF = [&](int c, uint32_t stg) {
        const size_t k0 = (size_t)c * 64;
        #pragma unroll
        for (int i = 0; i < 8; ++i) {
            int arr = i >> 1;
            int idx = ((i & 1) << 8) + t;
            int row = idx >> 3, kg = (idx & 7) * 8;
            CP16(stg + arr * D_ARR + (uint32_t)row * 144 + kg * 2,
                 srcF[arr] + (size_t)row * LH + k0 + kg);
        }
        CP_COMMIT();
    };
    auto convert = [&](uint32_t uvoff) {          // u at +0, v at +D_ARR; [l][e]
        #pragma unroll
        for (int ps = 0; ps < 4; ++ps) {
            int l = ql + ps * 16;
            uint32_t ad = uvoff + (uint32_t)l * 144 + (t & 15) * 8;
            float4 a = ra[ps], bb = rb[ps];
            union { uint2 v; __half x[4]; } U, V;
            U.x[0] = __float2half(a.x + bb.x);  V.x[0] = __float2half(a.x - bb.x);
            U.x[1] = __float2half(a.y + bb.y);  V.x[1] = __float2half(a.y - bb.y);
            U.x[2] = __float2half(a.z + bb.z);  V.x[2] = __float2half(a.z - bb.z);
            U.x[3] = __float2half(a.w + bb.w);  V.x[3] = __float2half(a.w - bb.w);
            *(uint2*)(smd + ad)         = U.v;
            *(uint2*)(smd + ad + D_ARR) = V.v;
        }
    };

    const uint32_t aoff = (uint32_t)(wr * 16 + (lane & 15)) * 144 + (lane >> 4) * 16;
    const uint32_t boff = (uint32_t)(lane & 15) * 144 + (lane >> 4) * 16;

    float acc[8][4];
    #pragma unroll
    for (int i = 0; i < 8; ++i)
        #pragma unroll
        for (int j = 0; j < 4; ++j) acc[i][j] = 0.f;

    LDGQ(0);
    issueF(0, sb);
    for (int c = 0; c < 32; ++c) {
        const uint32_t uvoff = 2 * F_STG + (uint32_t)(c & 1) * UV_STG;
        convert(uvoff);
        if (c < 31) {
            LDGQ((c + 1) * 64);
            issueF(c + 1, sb + (uint32_t)((c + 1) & 1) * F_STG);
            CP_WAIT1();
        } else CP_WAIT0();
        __syncthreads();
        const uint32_t fst = sb + (uint32_t)(c & 1) * F_STG;
        const uint32_t aHi = fst + grp * (2 * D_ARR) + aoff, aLo = aHi + D_ARR;
        const uint32_t bB  = sb + uvoff + grp * D_ARR + boff;
        #pragma unroll
        for (int ks = 0; ks < 4; ++ks) {
            uint32_t ah[4], al[4];
            ldsm4(ah, aHi + ks * 32);
            ldsm4(al, aLo + ks * 32);
            #pragma unroll
            for (int j = 0; j < 4; ++j) {
                uint32_t bv[4];
                ldsm4t(bv, bB + ks * 2304 + j * 32);    // 2304 = 16*144
                mma16816(acc[2 * j],     ah, bv);
                mma16816(acc[2 * j],     al, bv);
                mma16816(acc[2 * j + 1], ah, bv + 2);
                mma16816(acc[2 * j + 1], al, bv + 2);
            }
        }
        __syncthreads();
    }

    const int g = lane >> 2, q4 = lane & 3;
    float* xb = g_X + (size_t)bh * 8192;
    const int r0 = wr * 16 + g, r1 = r0 + 8;
    const int f2a = 2 * r0 - (r0 & 1) + 2 * grp;
    const int f2b = 2 * r1 - (r1 & 1) + 2 * grp;
    #pragma unroll
    for (int j = 0; j < 8; ++j) {
        int e0 = j * 8 + q4 * 2;
        xb[e0 * 128 + f2a]       = acc[j][0];
        xb[(e0 + 1) * 128 + f2a] = acc[j][1];
        xb[e0 * 128 + f2b]       = acc[j][2];
        xb[(e0 + 1) * 128 + f2b] = acc[j][3];
    }
}

// ---------------------------------------------------------------- Stage 2: mix
#define MIX_SMEM 98304       // Ws_r 32K | Ws_i 32K | Xs 32K
__global__ __launch_bounds__(256) void mix_kernel(const float* __restrict__ wr,
                                                  const float* __restrict__ wi) {
    extern __shared__ char sm[];
    float* Ws_r = (float*)sm;
    float* Ws_i = (float*)(sm + 32768);
    float* Xs   = (float*)(sm + 65536);
    const int h = blockIdx.x & 7, og = (blockIdx.x >> 3) & 7, bq = blockIdx.x >> 6;
    const int t = threadIdx.x;
    const int f2 = t & 31, ol = t >> 5;

    float acc[4][4];
    #pragma unroll
    for (int i = 0; i < 4; ++i)
        #pragma unroll
        for (int j = 0; j < 4; ++j) acc[i][j] = 0.f;

    for (int e0 = 0; e0 < 64; e0 += 16) {
        __syncthreads();
        #pragma unroll
        for (int i = 0; i < 8; ++i) {
            int c = t + i * 256;
            int row = c >> 4, m4 = (c & 15) * 4;
            int e = row >> 3, o = row & 7;
            size_t g = (((size_t)h * 64 + e0 + e) * 64 + og * 8 + o) * 64 + m4;
            *(float4*)&Ws_r[(e * 8 + o) * 64 + m4] = *(const float4*)&wr[g];
            *(float4*)&Ws_i[(e * 8 + o) * 64 + m4] = *(const float4*)&wi[g];
        }
        #pragma unroll
        for (int i = 0; i < 8; ++i) {
            int c = t + i * 256;
            int row = c >> 5, f4 = (c & 31) * 4;
            int b = row >> 4, e = row & 15;
            int bh = (bq * 4 + b) * 8 + h;
            *(float4*)&Xs[(b * 16 + e) * 128 + f4] =
                *(const float4*)&g_X[(size_t)bh * 8192 + (e0 + e) * 128 + f4];
        }
        __syncthreads();
        #pragma unroll 4
        for (int e = 0; e < 16; ++e) {
            float2 w_r = *(float2*)&Ws_r[(e * 8 + ol) * 64 + 2 * f2];
            float2 w_i = *(float2*)&Ws_i[(e * 8 + ol) * 64 + 2 * f2];
            #pragma unroll
            for (int b = 0; b < 4; ++b) {
                float4 x = *(float4*)&Xs[(b * 16 + e) * 128 + 4 * f2];
                acc[b][0] += x.x * w_r.x - x.y * w_i.x;
                acc[b][1] += x.x * w_i.x + x.y * w_r.x;
                acc[b][2] += x.z * w_r.y - x.w * w_i.y;
                acc[b][3] += x.z * w_i.y + x.w * w_r.y;
            }
        }
    }
    const float a0 = ((f2 == 0) ? (1.0f / 4096.0f) : (2.0f / 4096.0f)) * CSCALE;
    const float a1 = (2.0f / 4096.0f) * CSCALE;
    #pragma unroll
    for (int b = 0; b < 4; ++b) {
        size_t row = (size_t)((bq * 4 + b) * 8 + h) * 64 + og * 8 + ol;
        union { uint32_t u; __half x[2]; } p;
        p.x[0] = __float2half(a0 * acc[b][0]);
        p.x[1] = __float2half(-a0 * acc[b][1]);
        *(uint32_t*)&g_Ce[row * 64 + 2 * f2] = p.u;
        p.x[0] = __float2half(a1 * acc[b][2]);
        p.x[1] = __float2half(-a1 * acc[b][3]);
        *(uint32_t*)&g_Co[row * 64 + 2 * f2] = p.u;
    }
}

// ---------------------------------------------------------------- Stage 3: iDFT
// CTA = (bh, lq). In-warp E/O: warp tile = 16 rows x 32 l, both parities.
// Register combine -> direct 32B-segment stores. 1 sync per 64-l chunk.
#define IJ_ARR 9216                  // 64 rows * 144B
#define IA_SZ  (2 * IJ_ARR)          // Ce|Co = 18432
#define IG_SZ  (4 * IJ_ARR)          // Gte_hi|Gte_lo|Gto_hi|Gto_lo = 36864/stage
#define IDFT_SMEM (IA_SZ + 2 * IG_SZ)   // 92160

__global__ __launch_bounds__(256, 2) void idft_mma_kernel(float* __restrict__ out) {
    extern __shared__ char smi[];
    const uint32_t sb = smem_u32(smi);
    const int bh = blockIdx.x & 127, lq = blockIdx.x >> 7;   // lq 0..3
    const int t = threadIdx.x, w = t >> 5, lane = t & 31;
    const int w4 = w & 3, wh = w >> 2;        // row group / l-half
    const size_t pC = (size_t)bh * 64 * 64;

    const __half* srcA[2] = { g_Ce + pC, g_Co + pC };
    const __half* srcG[4] = { g_Gte_hi, g_Gte_lo, g_Gto_hi, g_Gto_lo };

    auto issueG = [&](int lc, uint32_t stg) {     // 64 l rows x 64 k, 4 arrays
        const size_t lG = (size_t)lc * 64 * 64;
        #pragma unroll
        for (int i = 0; i < 8; ++i) {
            int arr = i >> 1;
            int idx = ((i & 1) << 8) + t;
            int row = idx >> 3, kg = (idx & 7) * 8;
            CP16(stg + arr * IJ_ARR + (uint32_t)row * 144 + kg * 2,
                 srcG[arr] + lG + (size_t)row * 64 + kg);
        }
    };

    // prologue: A (2 arrays) + G(lq*8), one group
    #pragma unroll
    for (int i = 0; i < 4; ++i) {
        int arr = i >> 1;
        int idx = ((i & 1) << 8) + t;
        int row = idx >> 3, kg = (idx & 7) * 8;
        CP16(sb + arr * IJ_ARR + (uint32_t)row * 144 + kg * 2,
             srcA[arr] + (size_t)row * 64 + kg);
    }
    issueG(lq * 8, sb + IA_SZ);
    CP_COMMIT();

    const uint32_t aoff = (uint32_t)(w4 * 16 + (lane & 15)) * 144 + (lane >> 4) * 16;
    uint32_t boff[2];
    #pragma unroll
    for (int jl = 0; jl < 2; ++jl)
        boff[jl] = (uint32_t)(wh * 32 + jl * 16 + (lane >> 4) * 8 + (lane & 7)) * 144
                 + ((lane >> 3) & 1) * 16;
    const int g = lane >> 2, q4 = lane & 3;

    for (int cc = 0; cc < 8; ++cc) {
        const int lc = lq * 8 + cc;
        CP_WAIT0();
        __syncthreads();          // chunk cc data visible; all warps past chunk cc-1
        if (cc < 7) {
            issueG(lc + 1, sb + IA_SZ + (uint32_t)((cc + 1) & 1) * IG_SZ);
            CP_COMMIT();
        }
        const uint32_t gst = sb + IA_SZ + (uint32_t)(cc & 1) * IG_SZ;

        float accE[4][4], accO[4][4];
        #pragma unroll
        for (int i = 0; i < 4; ++i)
            #pragma unroll
            for (int j = 0; j < 4; ++j) { accE[i][j] = 0.f; accO[i][j] = 0.f; }

        #pragma unroll
        for (int p = 0; p < 2; ++p) {
            float (*acc)[4] = p ? accO : accE;
            const uint32_t aC = sb + (uint32_t)p * IJ_ARR + aoff;
            const uint32_t gb = gst + (uint32_t)(2 * p) * IJ_ARR;
            #pragma unroll
            for (int ks = 0; ks < 4; ++ks) {
                uint32_t ac[4];
                ldsm4(ac, aC + ks * 32);
                #pragma unroll
                for (int jl = 0; jl < 2; ++jl) {
                    uint32_t bh_[4], bl_[4];
                    ldsm4(bh_, gb + boff[jl] + ks * 32);
                    ldsm4(bl_, gb + IJ_ARR + boff[jl] + ks * 32);
                    mma16816(acc[2 * jl],     ac, bh_);
                    mma16816(acc[2 * jl],     ac, bl_);
                    mma16816(acc[2 * jl + 1], ac, bh_ + 2);
                    mma16816(acc[2 * jl + 1], ac, bl_ + 2);
                }
            }
        }

        // register combine + direct stores (4-lane groups form 32B segments)
        const int r0 = w4 * 16 + g;
        float* o0 = out + ((size_t)bh * 64 + r0) * LSEQ + lc * 64 + wh * 32 + q4 * 2;
        float* o1 = o0 + (size_t)8 * LSEQ;
        #pragma unroll
        for (int jj = 0; jj < 4; ++jj) {
            float e0 = accE[jj][0], e1 = accE[jj][1], o0v = accO[jj][0], o1v = accO[jj][1];
            float e2 = accE[jj][2], e3 = accE[jj][3], o2v = accO[jj][2], o3v = accO[jj][3];
            *(float2*)(o0 + jj * 8)      = make_float2((e0 + o0v) * CINV, (e1 + o1v) * CINV);
            *(float2*)(o0 + LH + jj * 8) = make_float2((e0 - o0v) * CINV, (e1 - o1v) * CINV);
            *(float2*)(o1 + jj * 8)      = make_float2((e2 + o2v) * CINV, (e3 + o3v) * CINV);
            *(float2*)(o1 + LH + jj * 8) = make_float2((e2 - o2v) * CINV, (e3 - o3v) * CINV);
        }
    }
}

// ---------------------------------------------------------------------------
extern "C" void kernel_launch(void* const* d_in, const int* in_sizes, int n_in,
                              void* d_out, int out_size) {
    const float* q = (const float*)d_in[0];
    const float* wr = nullptr;
    const float* wi = nullptr;
    for (int i = 0; i < n_in; ++i) {
        if (in_sizes[i] == 8 * 64 * 64 * 64) {
            if (!wr) wr = (const float*)d_in[i];
            else if (!wi) wi = (const float*)d_in[i];
        }
    }
    float* out = (float*)d_out;

    cudaFuncSetAttribute(dft_fused_kernel, cudaFuncAttributeMaxDynamicSharedMemorySize, DFT_SMEM);
    cudaFuncSetAttribute(mix_kernel,       cudaFuncAttributeMaxDynamicSharedMemorySize, MIX_SMEM);
    cudaFuncSetAttribute(idft_mma_kernel,  cudaFuncAttributeMaxDynamicSharedMemorySize, IDFT_SMEM);

    init_basis_kernel<<<512, 256>>>();
    dft_fused_kernel<<<NBH, 256, DFT_SMEM>>>(q);
    mix_kernel<<<256, 256, MIX_SMEM>>>(wr, wi);
    idft_mma_kernel<<<512, 256, IDFT_SMEM>>>(out);
}

// round 13
// speedup vs baseline: 1.2733x; 1.0034x over previous
#include <cuda_runtime.h>
#include <cuda_fp16.h>
#include <cstdint>
#include <cstddef>

#define LSEQ 4096
#define LH   2048
#define NBH  128
#define CSCALE 65536.0f
#define CINV  (1.0f / 65536.0f)

// ------------------------------------------------------------- gmem scratch
__device__ __half g_Fu_hi[64 * LH], g_Fu_lo[64 * LH];   // fwd basis even-f rows
__device__ __half g_Fv_hi[64 * LH], g_Fv_lo[64 * LH];   // fwd basis odd-f rows
__device__ __half g_Gte_hi[LH * 64], g_Gte_lo[LH * 64]; // inv basis even parity
__device__ __half g_Gto_hi[LH * 64], g_Gto_lo[LH * 64]; // inv basis odd parity
__device__ float  g_X[NBH * 64 * 128];                  // [bh][e][f2]
__device__ __half g_Ce[NBH * 64 * 64], g_Co[NBH * 64 * 64];   // C * 2^16

// ------------------------------------------------------------- helpers
__device__ __forceinline__ uint32_t smem_u32(const void* p) {
    uint32_t a;
    asm("{ .reg .u64 t; cvta.to.shared.u64 t, %1; cvt.u32.u64 %0, t; }" : "=r"(a) : "l"(p));
    return a;
}
__device__ __forceinline__ void split_fp16(float x, __half& hi, __half& lo) {
    hi = __float2half(x);
    lo = __float2half(x - __half2float(hi));
}
__device__ __forceinline__ void ldsm4(uint32_t* r, uint32_t addr) {
    asm volatile("ldmatrix.sync.aligned.m8n8.x4.shared.b16 {%0,%1,%2,%3}, [%4];"
                 : "=r"(r[0]), "=r"(r[1]), "=r"(r[2]), "=r"(r[3]) : "r"(addr));
}
__device__ __forceinline__ void ldsm4t(uint32_t* r, uint32_t addr) {
    asm volatile("ldmatrix.sync.aligned.m8n8.x4.trans.shared.b16 {%0,%1,%2,%3}, [%4];"
                 : "=r"(r[0]), "=r"(r[1]), "=r"(r[2]), "=r"(r[3]) : "r"(addr));
}
__device__ __forceinline__ void mma16816(float* d, const uint32_t* a, const uint32_t* b) {
    asm volatile("mma.sync.aligned.m16n8k16.row.col.f32.f16.f16.f32 "
                 "{%0,%1,%2,%3}, {%4,%5,%6,%7}, {%8,%9}, {%0,%1,%2,%3};"
                 : "+f"(d[0]), "+f"(d[1]), "+f"(d[2]), "+f"(d[3])
                 : "r"(a[0]), "r"(a[1]), "r"(a[2]), "r"(a[3]), "r"(b[0]), "r"(b[1]));
}
#define CP16(sa, gp) asm volatile("cp.async.cg.shared.global [%0], [%1], 16;" \
                                  :: "r"((uint32_t)(sa)), "l"(gp) : "memory")
#define CP_COMMIT()  asm volatile("cp.async.commit_group;" ::: "memory")
#define CP_WAIT0()   asm volatile("cp.async.wait_group 0;" ::: "memory")
#define CP_WAIT1()   asm volatile("cp.async.wait_group 1;" ::: "memory")

// ---------------------------------------------------------------- basis init
__global__ void init_basis_kernel() {
    int idx = blockIdx.x * 256 + threadIdx.x;      // < 131072
    {   // Fu/Fv rows ru = 2*fe + c (c=0 cos, c=1 -sin), half domain
        int ru = idx >> 11, l = idx & 2047;
        int fe = ru >> 1, c = ru & 1;
        float s, cs;
        __half hi, lo;
        sincospif((float)((l * (2 * fe)) & 4095) / 2048.0f, &s, &cs);
        split_fp16(c ? -s : cs, hi, lo);
        g_Fu_hi[ru * LH + l] = hi;  g_Fu_lo[ru * LH + l] = lo;
        sincospif((float)((l * (2 * fe + 1)) & 4095) / 2048.0f, &s, &cs);
        split_fp16(c ? -s : cs, hi, lo);
        g_Fv_hi[ru * LH + l] = hi;  g_Fv_lo[ru * LH + l] = lo;
    }
    {   // Gte/Gto: [l][kk=2*fe+c], c=0 cos, c=1 +sin
        int l = idx >> 6, kk = idx & 63;
        int fe = kk >> 1, c = kk & 1;
        float s, cs;
        __half hi, lo;
        sincospif((float)((l * (2 * fe)) & 4095) / 2048.0f, &s, &cs);
        split_fp16(c ? s : cs, hi, lo);
        g_Gte_hi[l * 64 + kk] = hi;  g_Gte_lo[l * 64 + kk] = lo;
        sincospif((float)((l * (2 * fe + 1)) & 4095) / 2048.0f, &s, &cs);
        split_fp16(c ? s : cs, hi, lo);
        g_Gto_hi[l * 64 + kk] = hi;  g_Gto_lo[l * 64 + kk] = lo;
    }
}

// ---------------------------------------------------------------- Stage 1: DFT
// CTA = (e-half, bh), grid 256. Each CTA: D[128 f2, 32 e], K=2048 in 32 chunks.
// Basis split hi/lo (2 passes); u/v single fp16 in [l][32e] tiles (80B rows).
#define D_ARR  9216                  // F array: 64 rows * 144B
#define F_STG  (4 * D_ARR)           // 36864
#define UV_ARR 5120                  // 64 rows * 80B
#define UV_STG (2 * UV_ARR)          // 10240
#define DFT_SMEM (2 * F_STG + 2 * UV_STG)   // 94208

__global__ __launch_bounds__(256, 2) void dft_fused_kernel(const float* __restrict__ q) {
    extern __shared__ char smd[];
    const uint32_t sb = smem_u32(smd);
    const int bh = blockIdx.x & 127, eh = blockIdx.x >> 7;   // e-half 0/1
    const int b = bh >> 3, h = bh & 7;
    const int t = threadIdx.x, w = t >> 5, lane = t & 31;
    const int grp = w >> 2, wr = w & 3;
    const float* qb = q + ((size_t)b * LSEQ * 8 + h) * 64 + eh * 32;

    const __half* srcF[4] = { g_Fu_hi, g_Fu_lo, g_Fv_hi, g_Fv_lo };

    const int ql = t >> 3, qe4 = (t & 7) * 4;   // 32 l rows per pass, 32 e
    float4 ra[2], rb[2];
    auto LDGQ = [&](int l0) {
        #pragma unroll
        for (int ps = 0; ps < 2; ++ps) {
            const float* p = qb + (size_t)(l0 + ql + ps * 32) * 512 + qe4;
            ra[ps] = *(const float4*)p;
            rb[ps] = *(const float4*)(p + (size_t)LH * 512);
        }
    };
    auto issueF = [&](int c, uint32_t stg) {
        const size_t k0 = (size_t)c * 64;
        #pragma unroll
        for (int i = 0; i < 8; ++i) {
            int arr = i >> 1;
            int idx = ((i & 1) << 8) + t;
            int row = idx >> 3, kg = (idx & 7) * 8;
            CP16(stg + arr * D_ARR + (uint32_t)row * 144 + kg * 2,
                 srcF[arr] + (size_t)row * LH + k0 + kg);
        }
        CP_COMMIT();
    };
    auto convert = [&](uint32_t uvoff) {          // u at +0, v at +UV_ARR; [l][32e]
        #pragma unroll
        for (int ps = 0; ps < 2; ++ps) {
            int l = ql + ps * 32;
            uint32_t ad = uvoff + (uint32_t)l * 80 + (t & 7) * 8;
            float4 a = ra[ps], bb = rb[ps];
            union { uint2 v; __half x[4]; } U, V;
            U.x[0] = __float2half(a.x + bb.x);  V.x[0] = __float2half(a.x - bb.x);
            U.x[1] = __float2half(a.y + bb.y);  V.x[1] = __float2half(a.y - bb.y);
            U.x[2] = __float2half(a.z + bb.z);  V.x[2] = __float2half(a.z - bb.z);
            U.x[3] = __float2half(a.w + bb.w);  V.x[3] = __float2half(a.w - bb.w);
            *(uint2*)(smd + ad)          = U.v;
            *(uint2*)(smd + ad + UV_ARR) = V.v;
        }
    };

    const uint32_t aoff = (uint32_t)(wr * 16 + (lane & 15)) * 144 + (lane >> 4) * 16;
    const uint32_t boff = (uint32_t)(lane & 15) * 80 + (lane >> 4) * 16;

    float acc[4][4];
    #pragma unroll
    for (int i = 0; i < 4; ++i)
        #pragma unroll
        for (int j = 0; j < 4; ++j) acc[i][j] = 0.f;

    LDGQ(0);
    issueF(0, sb);
    for (int c = 0; c < 32; ++c) {
        const uint32_t uvoff = 2 * F_STG + (uint32_t)(c & 1) * UV_STG;
        convert(uvoff);
        if (c < 31) {
            LDGQ((c + 1) * 64);
            issueF(c + 1, sb + (uint32_t)((c + 1) & 1) * F_STG);
            CP_WAIT1();
        } else CP_WAIT0();
        __syncthreads();
        const uint32_t fst = sb + (uint32_t)(c & 1) * F_STG;
        const uint32_t aHi = fst + grp * (2 * D_ARR) + aoff, aLo = aHi + D_ARR;
        const uint32_t bB  = sb + uvoff + grp * UV_ARR + boff;
        #pragma unroll
        for (int ks = 0; ks < 4; ++ks) {
            uint32_t ah[4], al[4];
            ldsm4(ah, aHi + ks * 32);
            ldsm4(al, aLo + ks * 32);
            #pragma unroll
            for (int j = 0; j < 2; ++j) {
                uint32_t bv[4];
                ldsm4t(bv, bB + ks * 1280 + j * 32);    // 1280 = 16*80
                mma16816(acc[2 * j],     ah, bv);
                mma16816(acc[2 * j],     al, bv);
                mma16816(acc[2 * j + 1], ah, bv + 2);
                mma16816(acc[2 * j + 1], al, bv + 2);
            }
        }
        __syncthreads();
    }

    const int g = lane >> 2, q4 = lane & 3;
    float* xb = g_X + (size_t)bh * 8192;
    const int r0 = wr * 16 + g, r1 = r0 + 8;
    const int f2a = 2 * r0 - (r0 & 1) + 2 * grp;
    const int f2b = 2 * r1 - (r1 & 1) + 2 * grp;
    #pragma unroll
    for (int jj = 0; jj < 4; ++jj) {
        int e0 = eh * 32 + jj * 8 + q4 * 2;
        xb[e0 * 128 + f2a]       = acc[jj][0];
        xb[(e0 + 1) * 128 + f2a] = acc[jj][1];
        xb[e0 * 128 + f2b]       = acc[jj][2];
        xb[(e0 + 1) * 128 + f2b] = acc[jj][3];
    }
}

// ---------------------------------------------------------------- Stage 2: mix
#define MIX_SMEM 98304       // Ws_r 32K | Ws_i 32K | Xs 32K
__global__ __launch_bounds__(256) void mix_kernel(const float* __restrict__ wr,
                                                  const float* __restrict__ wi) {
    extern __shared__ char sm[];
    float* Ws_r = (float*)sm;
    float* Ws_i = (float*)(sm + 32768);
    float* Xs   = (float*)(sm + 65536);
    const int h = blockIdx.x & 7, og = (blockIdx.x >> 3) & 7, bq = blockIdx.x >> 6;
    const int t = threadIdx.x;
    const int f2 = t & 31, ol = t >> 5;

    float acc[4][4];
    #pragma unroll
    for (int i = 0; i < 4; ++i)
        #pragma unroll
        for (int j = 0; j < 4; ++j) acc[i][j] = 0.f;

    for (int e0 = 0; e0 < 64; e0 += 16) {
        __syncthreads();
        #pragma unroll
        for (int i = 0; i < 8; ++i) {
            int c = t + i * 256;
            int row = c >> 4, m4 = (c & 15) * 4;
            int e = row >> 3, o = row & 7;
            size_t g = (((size_t)h * 64 + e0 + e) * 64 + og * 8 + o) * 64 + m4;
            *(float4*)&Ws_r[(e * 8 + o) * 64 + m4] = *(const float4*)&wr[g];
            *(float4*)&Ws_i[(e * 8 + o) * 64 + m4] = *(const float4*)&wi[g];
        }
        #pragma unroll
        for (int i = 0; i < 8; ++i) {
            int c = t + i * 256;
            int row = c >> 5, f4 = (c & 31) * 4;
            int b = row >> 4, e = row & 15;
            int bh = (bq * 4 + b) * 8 + h;
            *(float4*)&Xs[(b * 16 + e) * 128 + f4] =
                *(const float4*)&g_X[(size_t)bh * 8192 + (e0 + e) * 128 + f4];
        }
        __syncthreads();
        #pragma unroll 4
        for (int e = 0; e < 16; ++e) {
            float2 w_r = *(float2*)&Ws_r[(e * 8 + ol) * 64 + 2 * f2];
            float2 w_i = *(float2*)&Ws_i[(e * 8 + ol) * 64 + 2 * f2];
            #pragma unroll
            for (int b = 0; b < 4; ++b) {
                float4 x = *(float4*)&Xs[(b * 16 + e) * 128 + 4 * f2];
                acc[b][0] += x.x * w_r.x - x.y * w_i.x;
                acc[b][1] += x.x * w_i.x + x.y * w_r.x;
                acc[b][2] += x.z * w_r.y - x.w * w_i.y;
                acc[b][3] += x.z * w_i.y + x.w * w_r.y;
            }
        }
    }
    const float a0 = ((f2 == 0) ? (1.0f / 4096.0f) : (2.0f / 4096.0f)) * CSCALE;
    const float a1 = (2.0f / 4096.0f) * CSCALE;
    #pragma unroll
    for (int b = 0; b < 4; ++b) {
        size_t row = (size_t)((bq * 4 + b) * 8 + h) * 64 + og * 8 + ol;
        union { uint32_t u; __half x[2]; } p;
        p.x[0] = __float2half(a0 * acc[b][0]);
        p.x[1] = __float2half(-a0 * acc[b][1]);
        *(uint32_t*)&g_Ce[row * 64 + 2 * f2] = p.u;
        p.x[0] = __float2half(a1 * acc[b][2]);
        p.x[1] = __float2half(-a1 * acc[b][3]);
        *(uint32_t*)&g_Co[row * 64 + 2 * f2] = p.u;
    }
}

// ---------------------------------------------------------------- Stage 3: iDFT
// CTA = (bh-pair, lq), grid 256. Each G chunk staged once serves BOTH bh.
// In-warp E/O, register combine, direct 32B-segment stores, 1 sync/chunk.
#define IJ_ARR 9216                  // 64 rows * 144B
#define IA_SZ  (4 * IJ_ARR)          // Ce0|Co0|Ce1|Co1 = 36864
#define IG_SZ  (4 * IJ_ARR)          // Gte_hi|Gte_lo|Gto_hi|Gto_lo = 36864/stage
#define IDFT_SMEM (IA_SZ + 2 * IG_SZ)   // 110592

__global__ __launch_bounds__(256, 2) void idft_mma_kernel(float* __restrict__ out) {
    extern __shared__ char smi[];
    const uint32_t sb = smem_u32(smi);
    const int pp = blockIdx.x & 63, lq = blockIdx.x >> 6;   // bh-pair / l-quarter
    const int t = threadIdx.x, w = t >> 5, lane = t & 31;
    const int w4 = w & 3, wh = w >> 2;        // row group / l-half
    const size_t pC0 = (size_t)(pp * 2) * 64 * 64;

    const __half* srcA[4] = { g_Ce + pC0, g_Co + pC0,
                              g_Ce + pC0 + 4096, g_Co + pC0 + 4096 };
    const __half* srcG[4] = { g_Gte_hi, g_Gte_lo, g_Gto_hi, g_Gto_lo };

    auto issueG = [&](int lc, uint32_t stg) {     // 64 l rows x 64 k, 4 arrays
        const size_t lG = (size_t)lc * 64 * 64;
        #pragma unroll
        for (int i = 0; i < 8; ++i) {
            int arr = i >> 1;
            int idx = ((i & 1) << 8) + t;
            int row = idx >> 3, kg = (idx & 7) * 8;
            CP16(stg + arr * IJ_ARR + (uint32_t)row * 144 + kg * 2,
                 srcG[arr] + lG + (size_t)row * 64 + kg);
        }
    };

    // prologue: A (4 arrays: 2 bh x 2 parities) + G(lq*8), one group
    #pragma unroll
    for (int i = 0; i < 8; ++i) {
        int arr = i >> 1;
        int idx = ((i & 1) << 8) + t;
        int row = idx >> 3, kg = (idx & 7) * 8;
        CP16(sb + arr * IJ_ARR + (uint32_t)row * 144 + kg * 2,
             srcA[arr] + (size_t)row * 64 + kg);
    }
    issueG(lq * 8, sb + IA_SZ);
    CP_COMMIT();

    const uint32_t aoff = (uint32_t)(w4 * 16 + (lane & 15)) * 144 + (lane >> 4) * 16;
    uint32_t boff[2];
    #pragma unroll
    for (int jl = 0; jl < 2; ++jl)
        boff[jl] = (uint32_t)(wh * 32 + jl * 16 + (lane >> 4) * 8 + (lane & 7)) * 144
                 + ((lane >> 3) & 1) * 16;
    const int g = lane >> 2, q4 = lane & 3;

    for (int cc = 0; cc < 8; ++cc) {
        const int lc = lq * 8 + cc;
        CP_WAIT0();
        __syncthreads();          // chunk cc data visible; all warps past chunk cc-1
        if (cc < 7) {
            issueG(lc + 1, sb + IA_SZ + (uint32_t)((cc + 1) & 1) * IG_SZ);
            CP_COMMIT();
        }
        const uint32_t gst = sb + IA_SZ + (uint32_t)(cc & 1) * IG_SZ;

        #pragma unroll
        for (int bhx = 0; bhx < 2; ++bhx) {
            float accE[4][4], accO[4][4];
            #pragma unroll
            for (int i = 0; i < 4; ++i)
                #pragma unroll
                for (int j = 0; j < 4; ++j) { accE[i][j] = 0.f; accO[i][j] = 0.f; }

            #pragma unroll
            for (int p = 0; p < 2; ++p) {
                float (*acc)[4] = p ? accO : accE;
                const uint32_t aC = sb + (uint32_t)(bhx * 2 + p) * IJ_ARR + aoff;
                const uint32_t gb = gst + (uint32_t)(2 * p) * IJ_ARR;
                #pragma unroll
                for (int ks = 0; ks < 4; ++ks) {
                    uint32_t ac[4];
                    ldsm4(ac, aC + ks * 32);
                    #pragma unroll
                    for (int jl = 0; jl < 2; ++jl) {
                        uint32_t bh_[4], bl_[4];
                        ldsm4(bh_, gb + boff[jl] + ks * 32);
                        ldsm4(bl_, gb + IJ_ARR + boff[jl] + ks * 32);
                        mma16816(acc[2 * jl],     ac, bh_);
                        mma16816(acc[2 * jl],     ac, bl_);
                        mma16816(acc[2 * jl + 1], ac, bh_ + 2);
                        mma16816(acc[2 * jl + 1], ac, bl_ + 2);
                    }
                }
            }

            // register combine + direct stores (4-lane groups form 32B segments)
            const int bh = pp * 2 + bhx;
            const int r0 = w4 * 16 + g;
            float* o0 = out + ((size_t)bh * 64 + r0) * LSEQ + lc * 64 + wh * 32 + q4 * 2;
            float* o1 = o0 + (size_t)8 * LSEQ;
            #pragma unroll
            for (int jj = 0; jj < 4; ++jj) {
                float e0 = accE[jj][0], e1 = accE[jj][1];
                float o0v = accO[jj][0], o1v = accO[jj][1];
                float e2 = accE[jj][2], e3 = accE[jj][3];
                float o2v = accO[jj][2], o3v = accO[jj][3];
                *(float2*)(o0 + jj * 8)      = make_float2((e0 + o0v) * CINV, (e1 + o1v) * CINV);
                *(float2*)(o0 + LH + jj * 8) = make_float2((e0 - o0v) * CINV, (e1 - o1v) * CINV);
                *(float2*)(o1 + jj * 8)      = make_float2((e2 + o2v) * CINV, (e3 + o3v) * CINV);
                *(float2*)(o1 + LH + jj * 8) = make_float2((e2 - o2v) * CINV, (e3 - o3v) * CINV);
            }
        }
    }
}

// ---------------------------------------------------------------------------
extern "C" void kernel_launch(void* const* d_in, const int* in_sizes, int n_in,
                              void* d_out, int out_size) {
    const float* q = (const float*)d_in[0];
    const float* wr = nullptr;
    const float* wi = nullptr;
    for (int i = 0; i < n_in; ++i) {
        if (in_sizes[i] == 8 * 64 * 64 * 64) {
            if (!wr) wr = (const float*)d_in[i];
            else if (!wi) wi = (const float*)d_in[i];
        }
    }
    float* out = (float*)d_out;

    cudaFuncSetAttribute(dft_fused_kernel, cudaFuncAttributeMaxDynamicSharedMemorySize, DFT_SMEM);
    cudaFuncSetAttribute(mix_kernel,       cudaFuncAttributeMaxDynamicSharedMemorySize, MIX_SMEM);
    cudaFuncSetAttribute(idft_mma_kernel,  cudaFuncAttributeMaxDynamicSharedMemorySize, IDFT_SMEM);

    init_basis_kernel<<<512, 256>>>();
    dft_fused_kernel<<<256, 256, DFT_SMEM>>>(q);
    mix_kernel<<<256, 256, MIX_SMEM>>>(wr, wi);
    idft_mma_kernel<<<256, 256, IDFT_SMEM>>>(out);
}

// round 14
// speedup vs baseline: 1.3342x; 1.0478x over previous
#include <cuda_runtime.h>
#include <cuda_fp16.h>
#include <cstdint>
#include <cstddef>

#define LSEQ 4096
#define LH   2048
#define NBH  128
#define CSCALE 65536.0f
#define CINV  (1.0f / 65536.0f)

// ------------------------------------------------------------- gmem scratch
__device__ __half g_Fu[64 * LH], g_Fv[64 * LH];   // fwd basis even/odd-f rows
__device__ __half g_Gte[LH * 64], g_Gto[LH * 64]; // inv basis even/odd parity
__device__ float  g_X[NBH * 64 * 128];            // [bh][e][f2]
__device__ __half g_Ce[NBH * 64 * 64], g_Co[NBH * 64 * 64];   // C * 2^16

// ------------------------------------------------------------- helpers
__device__ __forceinline__ uint32_t smem_u32(const void* p) {
    uint32_t a;
    asm("{ .reg .u64 t; cvta.to.shared.u64 t, %1; cvt.u32.u64 %0, t; }" : "=r"(a) : "l"(p));
    return a;
}
__device__ __forceinline__ void ldsm4(uint32_t* r, uint32_t addr) {
    asm volatile("ldmatrix.sync.aligned.m8n8.x4.shared.b16 {%0,%1,%2,%3}, [%4];"
                 : "=r"(r[0]), "=r"(r[1]), "=r"(r[2]), "=r"(r[3]) : "r"(addr));
}
__device__ __forceinline__ void ldsm4t(uint32_t* r, uint32_t addr) {
    asm volatile("ldmatrix.sync.aligned.m8n8.x4.trans.shared.b16 {%0,%1,%2,%3}, [%4];"
                 : "=r"(r[0]), "=r"(r[1]), "=r"(r[2]), "=r"(r[3]) : "r"(addr));
}
__device__ __forceinline__ void mma16816(float* d, const uint32_t* a, const uint32_t* b) {
    asm volatile("mma.sync.aligned.m16n8k16.row.col.f32.f16.f16.f32 "
                 "{%0,%1,%2,%3}, {%4,%5,%6,%7}, {%8,%9}, {%0,%1,%2,%3};"
                 : "+f"(d[0]), "+f"(d[1]), "+f"(d[2]), "+f"(d[3])
                 : "r"(a[0]), "r"(a[1]), "r"(a[2]), "r"(a[3]), "r"(b[0]), "r"(b[1]));
}
#define CP16(sa, gp) asm volatile("cp.async.cg.shared.global [%0], [%1], 16;" \
                                  :: "r"((uint32_t)(sa)), "l"(gp) : "memory")
#define CP_COMMIT()  asm volatile("cp.async.commit_group;" ::: "memory")
#define CP_WAIT0()   asm volatile("cp.async.wait_group 0;" ::: "memory")
#define CP_WAIT1()   asm volatile("cp.async.wait_group 1;" ::: "memory")

// ---------------------------------------------------------------- basis init
__global__ void init_basis_kernel() {
    int idx = blockIdx.x * 256 + threadIdx.x;      // < 131072
    {   // Fu/Fv rows ru = 2*fe + c (c=0 cos, c=1 -sin), half domain
        int ru = idx >> 11, l = idx & 2047;
        int fe = ru >> 1, c = ru & 1;
        float s, cs;
        sincospif((float)((l * (2 * fe)) & 4095) / 2048.0f, &s, &cs);
        g_Fu[ru * LH + l] = __float2half(c ? -s : cs);
        sincospif((float)((l * (2 * fe + 1)) & 4095) / 2048.0f, &s, &cs);
        g_Fv[ru * LH + l] = __float2half(c ? -s : cs);
    }
    {   // Gte/Gto: [l][kk=2*fe+c], c=0 cos, c=1 +sin
        int l = idx >> 6, kk = idx & 63;
        int fe = kk >> 1, c = kk & 1;
        float s, cs;
        sincospif((float)((l * (2 * fe)) & 4095) / 2048.0f, &s, &cs);
        g_Gte[l * 64 + kk] = __float2half(c ? s : cs);
        sincospif((float)((l * (2 * fe + 1)) & 4095) / 2048.0f, &s, &cs);
        g_Gto[l * 64 + kk] = __float2half(c ? s : cs);
    }
}

// ---------------------------------------------------------------- Stage 1: DFT
// CTA = (e-half, bh), grid 256. D[128 f2, 32 e], K=2048 in 32 chunks.
// Single-pass fp16 basis; u/v single fp16 in [l][32e] tiles (80B rows).
#define D_ARR  9216                  // F array: 64 rows * 144B
#define F_STG  (2 * D_ARR)           // Fu|Fv = 18432
#define UV_ARR 5120                  // 64 rows * 80B
#define UV_STG (2 * UV_ARR)          // 10240
#define DFT_SMEM (2 * F_STG + 2 * UV_STG)   // 57344

__global__ __launch_bounds__(256, 2) void dft_fused_kernel(const float* __restrict__ q) {
    extern __shared__ char smd[];
    const uint32_t sb = smem_u32(smd);
    const int bh = blockIdx.x & 127, eh = blockIdx.x >> 7;   // e-half 0/1
    const int b = bh >> 3, h = bh & 7;
    const int t = threadIdx.x, w = t >> 5, lane = t & 31;
    const int grp = w >> 2, wr = w & 3;
    const float* qb = q + ((size_t)b * LSEQ * 8 + h) * 64 + eh * 32;

    const __half* srcF[2] = { g_Fu, g_Fv };

    const int ql = t >> 3, qe4 = (t & 7) * 4;   // 32 l rows per pass, 32 e
    float4 ra[2], rb[2];
    auto LDGQ = [&](int l0) {
        #pragma unroll
        for (int ps = 0; ps < 2; ++ps) {
            const float* p = qb + (size_t)(l0 + ql + ps * 32) * 512 + qe4;
            ra[ps] = *(const float4*)p;
            rb[ps] = *(const float4*)(p + (size_t)LH * 512);
        }
    };
    auto issueF = [&](int c, uint32_t stg) {
        const size_t k0 = (size_t)c * 64;
        #pragma unroll
        for (int i = 0; i < 4; ++i) {
            int arr = i >> 1;
            int idx = ((i & 1) << 8) + t;
            int row = idx >> 3, kg = (idx & 7) * 8;
            CP16(stg + arr * D_ARR + (uint32_t)row * 144 + kg * 2,
                 srcF[arr] + (size_t)row * LH + k0 + kg);
        }
        CP_COMMIT();
    };
    auto convert = [&](uint32_t uvoff) {          // u at +0, v at +UV_ARR; [l][32e]
        #pragma unroll
        for (int ps = 0; ps < 2; ++ps) {
            int l = ql + ps * 32;
            uint32_t ad = uvoff + (uint32_t)l * 80 + (t & 7) * 8;
            float4 a = ra[ps], bb = rb[ps];
            union { uint2 v; __half x[4]; } U, V;
            U.x[0] = __float2half(a.x + bb.x);  V.x[0] = __float2half(a.x - bb.x);
            U.x[1] = __float2half(a.y + bb.y);  V.x[1] = __float2half(a.y - bb.y);
            U.x[2] = __float2half(a.z + bb.z);  V.x[2] = __float2half(a.z - bb.z);
            U.x[3] = __float2half(a.w + bb.w);  V.x[3] = __float2half(a.w - bb.w);
            *(uint2*)(smd + ad)          = U.v;
            *(uint2*)(smd + ad + UV_ARR) = V.v;
        }
    };

    const uint32_t aoff = (uint32_t)(wr * 16 + (lane & 15)) * 144 + (lane >> 4) * 16;
    const uint32_t boff = (uint32_t)(lane & 15) * 80 + (lane >> 4) * 16;

    float acc[4][4];
    #pragma unroll
    for (int i = 0; i < 4; ++i)
        #pragma unroll
        for (int j = 0; j < 4; ++j) acc[i][j] = 0.f;

    LDGQ(0);
    issueF(0, sb);
    for (int c = 0; c < 32; ++c) {
        const uint32_t uvoff = 2 * F_STG + (uint32_t)(c & 1) * UV_STG;
        convert(uvoff);
        if (c < 31) {
            LDGQ((c + 1) * 64);
            issueF(c + 1, sb + (uint32_t)((c + 1) & 1) * F_STG);
            CP_WAIT1();
        } else CP_WAIT0();
        __syncthreads();
        const uint32_t aF = sb + (uint32_t)(c & 1) * F_STG + grp * D_ARR + aoff;
        const uint32_t bB = sb + uvoff + grp * UV_ARR + boff;
        #pragma unroll
        for (int ks = 0; ks < 4; ++ks) {
            uint32_t ah[4];
            ldsm4(ah, aF + ks * 32);
            #pragma unroll
            for (int j = 0; j < 2; ++j) {
                uint32_t bv[4];
                ldsm4t(bv, bB + ks * 1280 + j * 32);    // 1280 = 16*80
                mma16816(acc[2 * j],     ah, bv);
                mma16816(acc[2 * j + 1], ah, bv + 2);
            }
        }
        __syncthreads();
    }

    const int g = lane >> 2, q4 = lane & 3;
    float* xb = g_X + (size_t)bh * 8192;
    const int r0 = wr * 16 + g, r1 = r0 + 8;
    const int f2a = 2 * r0 - (r0 & 1) + 2 * grp;
    const int f2b = 2 * r1 - (r1 & 1) + 2 * grp;
    #pragma unroll
    for (int jj = 0; jj < 4; ++jj) {
        int e0 = eh * 32 + jj * 8 + q4 * 2;
        xb[e0 * 128 + f2a]       = acc[jj][0];
        xb[(e0 + 1) * 128 + f2a] = acc[jj][1];
        xb[e0 * 128 + f2b]       = acc[jj][2];
        xb[(e0 + 1) * 128 + f2b] = acc[jj][3];
    }
}

// ---------------------------------------------------------------- Stage 2: mix
// grid 512: (h, og: 8 o, bq: 2 b). W staged once per block; X 2 batches.
#define MIX_SMEM 81920       // Ws_r 32K | Ws_i 32K | Xs 16K
__global__ __launch_bounds__(256) void mix_kernel(const float* __restrict__ wr,
                                                  const float* __restrict__ wi) {
    extern __shared__ char sm[];
    float* Ws_r = (float*)sm;
    float* Ws_i = (float*)(sm + 32768);
    float* Xs   = (float*)(sm + 65536);      // [2b][16e][128]
    const int h = blockIdx.x & 7, og = (blockIdx.x >> 3) & 7, bq = blockIdx.x >> 6;
    const int t = threadIdx.x;
    const int f2 = t & 31, ol = t >> 5;

    float acc[2][4];
    #pragma unroll
    for (int i = 0; i < 2; ++i)
        #pragma unroll
        for (int j = 0; j < 4; ++j) acc[i][j] = 0.f;

    for (int e0 = 0; e0 < 64; e0 += 16) {
        __syncthreads();
        #pragma unroll
        for (int i = 0; i < 8; ++i) {
            int c = t + i * 256;
            int row = c >> 4, m4 = (c & 15) * 4;
            int e = row >> 3, o = row & 7;
            size_t g = (((size_t)h * 64 + e0 + e) * 64 + og * 8 + o) * 64 + m4;
            *(float4*)&Ws_r[(e * 8 + o) * 64 + m4] = *(const float4*)&wr[g];
            *(float4*)&Ws_i[(e * 8 + o) * 64 + m4] = *(const float4*)&wi[g];
        }
        #pragma unroll
        for (int i = 0; i < 4; ++i) {
            int c = t + i * 256;
            int row = c >> 5, f4 = (c & 31) * 4;
            int b = row >> 4, e = row & 15;
            int bh = (bq * 2 + b) * 8 + h;
            *(float4*)&Xs[(b * 16 + e) * 128 + f4] =
                *(const float4*)&g_X[(size_t)bh * 8192 + (e0 + e) * 128 + f4];
        }
        __syncthreads();
        #pragma unroll 4
        for (int e = 0; e < 16; ++e) {
            float2 w_r = *(float2*)&Ws_r[(e * 8 + ol) * 64 + 2 * f2];
            float2 w_i = *(float2*)&Ws_i[(e * 8 + ol) * 64 + 2 * f2];
            #pragma unroll
            for (int b = 0; b < 2; ++b) {
                float4 x = *(float4*)&Xs[(b * 16 + e) * 128 + 4 * f2];
                acc[b][0] += x.x * w_r.x - x.y * w_i.x;
                acc[b][1] += x.x * w_i.x + x.y * w_r.x;
                acc[b][2] += x.z * w_r.y - x.w * w_i.y;
                acc[b][3] += x.z * w_i.y + x.w * w_r.y;
            }
        }
    }
    const float a0 = ((f2 == 0) ? (1.0f / 4096.0f) : (2.0f / 4096.0f)) * CSCALE;
    const float a1 = (2.0f / 4096.0f) * CSCALE;
    #pragma unroll
    for (int b = 0; b < 2; ++b) {
        size_t row = (size_t)((bq * 2 + b) * 8 + h) * 64 + og * 8 + ol;
        union { uint32_t u; __half x[2]; } p;
        p.x[0] = __float2half(a0 * acc[b][0]);
        p.x[1] = __float2half(-a0 * acc[b][1]);
        *(uint32_t*)&g_Ce[row * 64 + 2 * f2] = p.u;
        p.x[0] = __float2half(a1 * acc[b][2]);
        p.x[1] = __float2half(-a1 * acc[b][3]);
        *(uint32_t*)&g_Co[row * 64 + 2 * f2] = p.u;
    }
}

// ---------------------------------------------------------------- Stage 3: iDFT
// CTA = (bh, lq), grid 512. Single-pass fp16 basis. In-warp E/O, register
// combine, direct 32B-segment stores, 1 sync per 64-l chunk. smem 54KB.
#define IJ_ARR 9216                  // 64 rows * 144B
#define IA_SZ  (2 * IJ_ARR)          // Ce|Co = 18432
#define IG_SZ  (2 * IJ_ARR)          // Gte|Gto per stage = 18432
#define IDFT_SMEM (IA_SZ + 2 * IG_SZ)   // 55296

__global__ __launch_bounds__(256, 3) void idft_mma_kernel(float* __restrict__ out) {
    extern __shared__ char smi[];
    const uint32_t sb = smem_u32(smi);
    const int bh = blockIdx.x & 127, lq = blockIdx.x >> 7;   // lq 0..3
    const int t = threadIdx.x, w = t >> 5, lane = t & 31;
    const int w4 = w & 3, wh = w >> 2;        // row group / l-half
    const size_t pC = (size_t)bh * 64 * 64;

    const __half* srcA[2] = { g_Ce + pC, g_Co + pC };
    const __half* srcG[2] = { g_Gte, g_Gto };

    auto issueG = [&](int lc, uint32_t stg) {     // 64 l rows x 64 k, 2 arrays
        const size_t lG = (size_t)lc * 64 * 64;
        #pragma unroll
        for (int i = 0; i < 4; ++i) {
            int arr = i >> 1;
            int idx = ((i & 1) << 8) + t;
            int row = idx >> 3, kg = (idx & 7) * 8;
            CP16(stg + arr * IJ_ARR + (uint32_t)row * 144 + kg * 2,
                 srcG[arr] + lG + (size_t)row * 64 + kg);
        }
    };

    // prologue: A (2 arrays) + G(lq*8), one group
    #pragma unroll
    for (int i = 0; i < 4; ++i) {
        int arr = i >> 1;
        int idx = ((i & 1) << 8) + t;
        int row = idx >> 3, kg = (idx & 7) * 8;
        CP16(sb + arr * IJ_ARR + (uint32_t)row * 144 + kg * 2,
             srcA[arr] + (size_t)row * 64 + kg);
    }
    issueG(lq * 8, sb + IA_SZ);
    CP_COMMIT();

    const uint32_t aoff = (uint32_t)(w4 * 16 + (lane & 15)) * 144 + (lane >> 4) * 16;
    uint32_t boff[2];
    #pragma unroll
    for (int jl = 0; jl < 2; ++jl)
        boff[jl] = (uint32_t)(wh * 32 + jl * 16 + (lane >> 4) * 8 + (lane & 7)) * 144
                 + ((lane >> 3) & 1) * 16;
    const int g = lane >> 2, q4 = lane & 3;

    for (int cc = 0; cc < 8; ++cc) {
        const int lc = lq * 8 + cc;
        CP_WAIT0();
        __syncthreads();          // chunk cc data visible; all warps past chunk cc-1
        if (cc < 7) {
            issueG(lc + 1, sb + IA_SZ + (uint32_t)((cc + 1) & 1) * IG_SZ);
            CP_COMMIT();
        }
        const uint32_t gst = sb + IA_SZ + (uint32_t)(cc & 1) * IG_SZ;

        float accE[4][4], accO[4][4];
        #pragma unroll
        for (int i = 0; i < 4; ++i)
            #pragma unroll
            for (int j = 0; j < 4; ++j) { accE[i][j] = 0.f; accO[i][j] = 0.f; }

        #pragma unroll
        for (int p = 0; p < 2; ++p) {
            float (*acc)[4] = p ? accO : accE;
            const uint32_t aC = sb + (uint32_t)p * IJ_ARR + aoff;
            const uint32_t gb = gst + (uint32_t)p * IJ_ARR;
            #pragma unroll
            for (int ks = 0; ks < 4; ++ks) {
                uint32_t ac[4];
                ldsm4(ac, aC + ks * 32);
                #pragma unroll
                for (int jl = 0; jl < 2; ++jl) {
                    uint32_t bh_[4];
                    ldsm4(bh_, gb + boff[jl] + ks * 32);
                    mma16816(acc[2 * jl],     ac, bh_);
                    mma16816(acc[2 * jl + 1], ac, bh_ + 2);
                }
            }
        }

        // register combine + direct stores (4-lane groups form 32B segments)
        const int r0 = w4 * 16 + g;
        float* o0 = out + ((size_t)bh * 64 + r0) * LSEQ + lc * 64 + wh * 32 + q4 * 2;
        float* o1 = o0 + (size_t)8 * LSEQ;
        #pragma unroll
        for (int jj = 0; jj < 4; ++jj) {
            float e0 = accE[jj][0], e1 = accE[jj][1], o0v = accO[jj][0], o1v = accO[jj][1];
            float e2 = accE[jj][2], e3 = accE[jj][3], o2v = accO[jj][2], o3v = accO[jj][3];
            *(float2*)(o0 + jj * 8)      = make_float2((e0 + o0v) * CINV, (e1 + o1v) * CINV);
            *(float2*)(o0 + LH + jj * 8) = make_float2((e0 - o0v) * CINV, (e1 - o1v) * CINV);
            *(float2*)(o1 + jj * 8)      = make_float2((e2 + o2v) * CINV, (e3 + o3v) * CINV);
            *(float2*)(o1 + LH + jj * 8) = make_float2((e2 - o2v) * CINV, (e3 - o3v) * CINV);
        }
    }
}

// ---------------------------------------------------------------------------
extern "C" void kernel_launch(void* const* d_in, const int* in_sizes, int n_in,
                              void* d_out, int out_size) {
    const float* q = (const float*)d_in[0];
    const float* wr = nullptr;
    const float* wi = nullptr;
    for (int i = 0; i < n_in; ++i) {
        if (in_sizes[i] == 8 * 64 * 64 * 64) {
            if (!wr) wr = (const float*)d_in[i];
            else if (!wi) wi = (const float*)d_in[i];
        }
    }
    float* out = (float*)d_out;

    cudaFuncSetAttribute(dft_fused_kernel, cudaFuncAttributeMaxDynamicSharedMemorySize, DFT_SMEM);
    cudaFuncSetAttribute(mix_kernel,       cudaFuncAttributeMaxDynamicSharedMemorySize, MIX_SMEM);
    cudaFuncSetAttribute(idft_mma_kernel,  cudaFuncAttributeMaxDynamicSharedMemorySize, IDFT_SMEM);

    init_basis_kernel<<<512, 256>>>();
    dft_fused_kernel<<<256, 256, DFT_SMEM>>>(q);
    mix_kernel<<<512, 256, MIX_SMEM>>>(wr, wi);
    idft_mma_kernel<<<512, 256, IDFT_SMEM>>>(out);
}

// round 15
// speedup vs baseline: 1.4168x; 1.0619x over previous
#include <cuda_runtime.h>
#include <cuda_fp16.h>
#include <cstdint>
#include <cstddef>

#define LSEQ 4096
#define LH   2048
#define NBH  128
#define CSCALE 65536.0f
#define CINV  (1.0f / 65536.0f)

// ------------------------------------------------------------- gmem scratch
__device__ __half g_Fu[64 * LH], g_Fv[64 * LH];   // fwd basis even/odd-f rows
__device__ __half g_Gte[LH * 64], g_Gto[LH * 64]; // inv basis even/odd parity
__device__ float  g_X[NBH * 64 * 128];            // [bh][e][f2]
__device__ __half g_Ce[NBH * 64 * 64], g_Co[NBH * 64 * 64];   // C * 2^16

// ------------------------------------------------------------- helpers
__device__ __forceinline__ uint32_t smem_u32(const void* p) {
    uint32_t a;
    asm("{ .reg .u64 t; cvta.to.shared.u64 t, %1; cvt.u32.u64 %0, t; }" : "=r"(a) : "l"(p));
    return a;
}
__device__ __forceinline__ void ldsm4(uint32_t* r, uint32_t addr) {
    asm volatile("ldmatrix.sync.aligned.m8n8.x4.shared.b16 {%0,%1,%2,%3}, [%4];"
                 : "=r"(r[0]), "=r"(r[1]), "=r"(r[2]), "=r"(r[3]) : "r"(addr));
}
__device__ __forceinline__ void ldsm4t(uint32_t* r, uint32_t addr) {
    asm volatile("ldmatrix.sync.aligned.m8n8.x4.trans.shared.b16 {%0,%1,%2,%3}, [%4];"
                 : "=r"(r[0]), "=r"(r[1]), "=r"(r[2]), "=r"(r[3]) : "r"(addr));
}
__device__ __forceinline__ void mma16816(float* d, const uint32_t* a, const uint32_t* b) {
    asm volatile("mma.sync.aligned.m16n8k16.row.col.f32.f16.f16.f32 "
                 "{%0,%1,%2,%3}, {%4,%5,%6,%7}, {%8,%9}, {%0,%1,%2,%3};"
                 : "+f"(d[0]), "+f"(d[1]), "+f"(d[2]), "+f"(d[3])
                 : "r"(a[0]), "r"(a[1]), "r"(a[2]), "r"(a[3]), "r"(b[0]), "r"(b[1]));
}
#define CP16(sa, gp) asm volatile("cp.async.cg.shared.global [%0], [%1], 16;" \
                                  :: "r"((uint32_t)(sa)), "l"(gp) : "memory")
#define CP_COMMIT()  asm volatile("cp.async.commit_group;" ::: "memory")
#define CP_WAIT0()   asm volatile("cp.async.wait_group 0;" ::: "memory")

// ---------------------------------------------------------------- basis init
__global__ void init_basis_kernel() {
    int idx = blockIdx.x * 256 + threadIdx.x;      // < 131072
    {   // Fu/Fv rows ru = 2*fe + c (c=0 cos, c=1 -sin), half domain
        int ru = idx >> 11, l = idx & 2047;
        int fe = ru >> 1, c = ru & 1;
        float s, cs;
        sincospif((float)((l * (2 * fe)) & 4095) / 2048.0f, &s, &cs);
        g_Fu[ru * LH + l] = __float2half(c ? -s : cs);
        sincospif((float)((l * (2 * fe + 1)) & 4095) / 2048.0f, &s, &cs);
        g_Fv[ru * LH + l] = __float2half(c ? -s : cs);
    }
    {   // Gte/Gto: [l][kk=2*fe+c], c=0 cos, c=1 +sin
        int l = idx >> 6, kk = idx & 63;
        int fe = kk >> 1, c = kk & 1;
        float s, cs;
        sincospif((float)((l * (2 * fe)) & 4095) / 2048.0f, &s, &cs);
        g_Gte[l * 64 + kk] = __float2half(c ? s : cs);
        sincospif((float)((l * (2 * fe + 1)) & 4095) / 2048.0f, &s, &cs);
        g_Gto[l * 64 + kk] = __float2half(c ? s : cs);
    }
}

// ---------------------------------------------------------------- Stage 1: DFT
// CTA = (e-half, bh), grid 256. D[128 f2, 32 e], K=2048 in 16 chunks of 128.
// 1 sync/chunk: issueF(c+1) AFTER sync (all warps past MMA(c-1) -> stage safe).
#define D_ARR  17408                 // F array: 64 rows * 272B (256B data + 16 pad)
#define F_STG  (2 * D_ARR)           // Fu|Fv = 34816
#define UV_ARR 10240                 // 128 rows * 80B
#define UV_STG (2 * UV_ARR)          // 20480
#define DFT_SMEM (2 * F_STG + 2 * UV_STG)   // 110592

__global__ __launch_bounds__(256, 2) void dft_fused_kernel(const float* __restrict__ q) {
    extern __shared__ char smd[];
    const uint32_t sb = smem_u32(smd);
    const int bh = blockIdx.x & 127, eh = blockIdx.x >> 7;   // e-half 0/1
    const int b = bh >> 3, h = bh & 7;
    const int t = threadIdx.x, w = t >> 5, lane = t & 31;
    const int grp = w >> 2, wr = w & 3;
    const float* qb = q + ((size_t)b * LSEQ * 8 + h) * 64 + eh * 32;

    const __half* srcF[2] = { g_Fu, g_Fv };

    const int ql = t >> 3, qe4 = (t & 7) * 4;   // 32 l rows per pass, 32 e
    float4 ra[4], rb[4];
    auto LDGQ = [&](int l0) {
        #pragma unroll
        for (int ps = 0; ps < 4; ++ps) {
            const float* p = qb + (size_t)(l0 + ql + ps * 32) * 512 + qe4;
            ra[ps] = *(const float4*)p;
            rb[ps] = *(const float4*)(p + (size_t)LH * 512);
        }
    };
    auto issueF = [&](int c, uint32_t stg) {     // 64 rows x 128 k per array
        const size_t k0 = (size_t)c * 128;
        #pragma unroll
        for (int i = 0; i < 8; ++i) {
            int arr = i >> 2;
            int idx = ((i & 3) << 8) + t;
            int row = idx >> 4, kg = (idx & 15) * 8;
            CP16(stg + arr * D_ARR + (uint32_t)row * 272 + kg * 2,
                 srcF[arr] + (size_t)row * LH + k0 + kg);
        }
        CP_COMMIT();
    };
    auto convert = [&](uint32_t uvoff) {          // u at +0, v at +UV_ARR; [128 l][32e]
        #pragma unroll
        for (int ps = 0; ps < 4; ++ps) {
            int l = ql + ps * 32;
            uint32_t ad = uvoff + (uint32_t)l * 80 + (t & 7) * 8;
            float4 a = ra[ps], bb = rb[ps];
            union { uint2 v; __half x[4]; } U, V;
            U.x[0] = __float2half(a.x + bb.x);  V.x[0] = __float2half(a.x - bb.x);
            U.x[1] = __float2half(a.y + bb.y);  V.x[1] = __float2half(a.y - bb.y);
            U.x[2] = __float2half(a.z + bb.z);  V.x[2] = __float2half(a.z - bb.z);
            U.x[3] = __float2half(a.w + bb.w);  V.x[3] = __float2half(a.w - bb.w);
            *(uint2*)(smd + ad)          = U.v;
            *(uint2*)(smd + ad + UV_ARR) = V.v;
        }
    };

    const uint32_t aoff = (uint32_t)(wr * 16 + (lane & 15)) * 272 + (lane >> 4) * 16;
    const uint32_t boff = (uint32_t)(lane & 15) * 80 + (lane >> 4) * 16;

    float acc[4][4];
    #pragma unroll
    for (int i = 0; i < 4; ++i)
        #pragma unroll
        for (int j = 0; j < 4; ++j) acc[i][j] = 0.f;

    LDGQ(0);
    issueF(0, sb);
    for (int c = 0; c < 16; ++c) {
        const uint32_t uvoff = 2 * F_STG + (uint32_t)(c & 1) * UV_STG;
        convert(uvoff);                       // write uv(c); MMA(c-1) reads other buf
        if (c < 15) LDGQ((c + 1) * 128);      // register prefetch
        CP_WAIT0();                           // F(c) landed
        __syncthreads();                      // all warps past MMA(c-1), uv(c) visible
        if (c < 15) issueF(c + 1, sb + (uint32_t)((c + 1) & 1) * F_STG);
        const uint32_t aF = sb + (uint32_t)(c & 1) * F_STG + grp * D_ARR + aoff;
        const uint32_t bB = sb + uvoff + grp * UV_ARR + boff;
        #pragma unroll
        for (int ks = 0; ks < 8; ++ks) {
            uint32_t ah[4];
            ldsm4(ah, aF + ks * 32);
            #pragma unroll
            for (int j = 0; j < 2; ++j) {
                uint32_t bv[4];
                ldsm4t(bv, bB + ks * 1280 + j * 32);    // 1280 = 16*80
                mma16816(acc[2 * j],     ah, bv);
                mma16816(acc[2 * j + 1], ah, bv + 2);
            }
        }
    }

    const int g = lane >> 2, q4 = lane & 3;
    float* xb = g_X + (size_t)bh * 8192;
    const int r0 = wr * 16 + g, r1 = r0 + 8;
    const int f2a = 2 * r0 - (r0 & 1) + 2 * grp;
    const int f2b = 2 * r1 - (r1 & 1) + 2 * grp;
    #pragma unroll
    for (int jj = 0; jj < 4; ++jj) {
        int e0 = eh * 32 + jj * 8 + q4 * 2;
        xb[e0 * 128 + f2a]       = acc[jj][0];
        xb[(e0 + 1) * 128 + f2a] = acc[jj][1];
        xb[e0 * 128 + f2b]       = acc[jj][2];
        xb[(e0 + 1) * 128 + f2b] = acc[jj][3];
    }
}

// ---------------------------------------------------------------- Stage 2: mix
// grid 256: (h, og: 8 o, bq: 4 b). W staged once per block (measured-good config).
#define MIX_SMEM 98304       // Ws_r 32K | Ws_i 32K | Xs 32K
__global__ __launch_bounds__(256) void mix_kernel(const float* __restrict__ wr,
                                                  const float* __restrict__ wi) {
    extern __shared__ char sm[];
    float* Ws_r = (float*)sm;
    float* Ws_i = (float*)(sm + 32768);
    float* Xs   = (float*)(sm + 65536);
    const int h = blockIdx.x & 7, og = (blockIdx.x >> 3) & 7, bq = blockIdx.x >> 6;
    const int t = threadIdx.x;
    const int f2 = t & 31, ol = t >> 5;

    float acc[4][4];
    #pragma unroll
    for (int i = 0; i < 4; ++i)
        #pragma unroll
        for (int j = 0; j < 4; ++j) acc[i][j] = 0.f;

    for (int e0 = 0; e0 < 64; e0 += 16) {
        __syncthreads();
        #pragma unroll
        for (int i = 0; i < 8; ++i) {
            int c = t + i * 256;
            int row = c >> 4, m4 = (c & 15) * 4;
            int e = row >> 3, o = row & 7;
            size_t g = (((size_t)h * 64 + e0 + e) * 64 + og * 8 + o) * 64 + m4;
            *(float4*)&Ws_r[(e * 8 + o) * 64 + m4] = *(const float4*)&wr[g];
            *(float4*)&Ws_i[(e * 8 + o) * 64 + m4] = *(const float4*)&wi[g];
        }
        #pragma unroll
        for (int i = 0; i < 8; ++i) {
            int c = t + i * 256;
            int row = c >> 5, f4 = (c & 31) * 4;
            int b = row >> 4, e = row & 15;
            int bh = (bq * 4 + b) * 8 + h;
            *(float4*)&Xs[(b * 16 + e) * 128 + f4] =
                *(const float4*)&g_X[(size_t)bh * 8192 + (e0 + e) * 128 + f4];
        }
        __syncthreads();
        #pragma unroll 4
        for (int e = 0; e < 16; ++e) {
            float2 w_r = *(float2*)&Ws_r[(e * 8 + ol) * 64 + 2 * f2];
            float2 w_i = *(float2*)&Ws_i[(e * 8 + ol) * 64 + 2 * f2];
            #pragma unroll
            for (int b = 0; b < 4; ++b) {
                float4 x = *(float4*)&Xs[(b * 16 + e) * 128 + 4 * f2];
                acc[b][0] += x.x * w_r.x - x.y * w_i.x;
                acc[b][1] += x.x * w_i.x + x.y * w_r.x;
                acc[b][2] += x.z * w_r.y - x.w * w_i.y;
                acc[b][3] += x.z * w_i.y + x.w * w_r.y;
            }
        }
    }
    const float a0 = ((f2 == 0) ? (1.0f / 4096.0f) : (2.0f / 4096.0f)) * CSCALE;
    const float a1 = (2.0f / 4096.0f) * CSCALE;
    #pragma unroll
    for (int b = 0; b < 4; ++b) {
        size_t row = (size_t)((bq * 4 + b) * 8 + h) * 64 + og * 8 + ol;
        union { uint32_t u; __half x[2]; } p;
        p.x[0] = __float2half(a0 * acc[b][0]);
        p.x[1] = __float2half(-a0 * acc[b][1]);
        *(uint32_t*)&g_Ce[row * 64 + 2 * f2] = p.u;
        p.x[0] = __float2half(a1 * acc[b][2]);
        p.x[1] = __float2half(-a1 * acc[b][3]);
        *(uint32_t*)&g_Co[row * 64 + 2 * f2] = p.u;
    }
}

// ---------------------------------------------------------------- Stage 3: iDFT
// CTA = (bh, lq), grid 512 (R14 config, measured 41.4us). 1 sync/chunk.
#define IJ_ARR 9216                  // 64 rows * 144B
#define IA_SZ  (2 * IJ_ARR)          // Ce|Co = 18432
#define IG_SZ  (2 * IJ_ARR)          // Gte|Gto per stage = 18432
#define IDFT_SMEM (IA_SZ + 2 * IG_SZ)   // 55296

__global__ __launch_bounds__(256, 3) void idft_mma_kernel(float* __restrict__ out) {
    extern __shared__ char smi[];
    const uint32_t sb = smem_u32(smi);
    const int bh = blockIdx.x & 127, lq = blockIdx.x >> 7;   // lq 0..3
    const int t = threadIdx.x, w = t >> 5, lane = t & 31;
    const int w4 = w & 3, wh = w >> 2;        // row group / l-half
    const size_t pC = (size_t)bh * 64 * 64;

    const __half* srcA[2] = { g_Ce + pC, g_Co + pC };
    const __half* srcG[2] = { g_Gte, g_Gto };

    auto issueG = [&](int lc, uint32_t stg) {     // 64 l rows x 64 k, 2 arrays
        const size_t lG = (size_t)lc * 64 * 64;
        #pragma unroll
        for (int i = 0; i < 4; ++i) {
            int arr = i >> 1;
            int idx = ((i & 1) << 8) + t;
            int row = idx >> 3, kg = (idx & 7) * 8;
            CP16(stg + arr * IJ_ARR + (uint32_t)row * 144 + kg * 2,
                 srcG[arr] + lG + (size_t)row * 64 + kg);
        }
    };

    // prologue: A (2 arrays) + G(lq*8), one group
    #pragma unroll
    for (int i = 0; i < 4; ++i) {
        int arr = i >> 1;
        int idx = ((i & 1) << 8) + t;
        int row = idx >> 3, kg = (idx & 7) * 8;
        CP16(sb + arr * IJ_ARR + (uint32_t)row * 144 + kg * 2,
             srcA[arr] + (size_t)row * 64 + kg);
    }
    issueG(lq * 8, sb + IA_SZ);
    CP_COMMIT();

    const uint32_t aoff = (uint32_t)(w4 * 16 + (lane & 15)) * 144 + (lane >> 4) * 16;
    uint32_t boff[2];
    #pragma unroll
    for (int jl = 0; jl < 2; ++jl)
        boff[jl] = (uint32_t)(wh * 32 + jl * 16 + (lane >> 4) * 8 + (lane & 7)) * 144
                 + ((lane >> 3) & 1) * 16;
    const int g = lane >> 2, q4 = lane & 3;

    for (int cc = 0; cc < 8; ++cc) {
        const int lc = lq * 8 + cc;
        CP_WAIT0();
        __syncthreads();          // chunk cc data visible; all warps past chunk cc-1
        if (cc < 7) {
            issueG(lc + 1, sb + IA_SZ + (uint32_t)((cc + 1) & 1) * IG_SZ);
            CP_COMMIT();
        }
        const uint32_t gst = sb + IA_SZ + (uint32_t)(cc & 1) * IG_SZ;

        float accE[4][4], accO[4][4];
        #pragma unroll
        for (int i = 0; i < 4; ++i)
            #pragma unroll
            for (int j = 0; j < 4; ++j) { accE[i][j] = 0.f; accO[i][j] = 0.f; }

        #pragma unroll
        for (int p = 0; p < 2; ++p) {
            float (*acc)[4] = p ? accO : accE;
            const uint32_t aC = sb + (uint32_t)p * IJ_ARR + aoff;
            const uint32_t gb = gst + (uint32_t)p * IJ_ARR;
            #pragma unroll
            for (int ks = 0; ks < 4; ++ks) {
                uint32_t ac[4];
                ldsm4(ac, aC + ks * 32);
                #pragma unroll
                for (int jl = 0; jl < 2; ++jl) {
                    uint32_t bh_[4];
                    ldsm4(bh_, gb + boff[jl] + ks * 32);
                    mma16816(acc[2 * jl],     ac, bh_);
                    mma16816(acc[2 * jl + 1], ac, bh_ + 2);
                }
            }
        }

        // register combine + direct stores (4-lane groups form 32B segments)
        const int r0 = w4 * 16 + g;
        float* o0 = out + ((size_t)bh * 64 + r0) * LSEQ + lc * 64 + wh * 32 + q4 * 2;
        float* o1 = o0 + (size_t)8 * LSEQ;
        #pragma unroll
        for (int jj = 0; jj < 4; ++jj) {
            float e0 = accE[jj][0], e1 = accE[jj][1], o0v = accO[jj][0], o1v = accO[jj][1];
            float e2 = accE[jj][2], e3 = accE[jj][3], o2v = accO[jj][2], o3v = accO[jj][3];
            *(float2*)(o0 + jj * 8)      = make_float2((e0 + o0v) * CINV, (e1 + o1v) * CINV);
            *(float2*)(o0 + LH + jj * 8) = make_float2((e0 - o0v) * CINV, (e1 - o1v) * CINV);
            *(float2*)(o1 + jj * 8)      = make_float2((e2 + o2v) * CINV, (e3 + o3v) * CINV);
            *(float2*)(o1 + LH + jj * 8) = make_float2((e2 - o2v) * CINV, (e3 - o3v) * CINV);
        }
    }
}

// ---------------------------------------------------------------------------
extern "C" void kernel_launch(void* const* d_in, const int* in_sizes, int n_in,
                              void* d_out, int out_size) {
    const float* q = (const float*)d_in[0];
    const float* wr = nullptr;
    const float* wi = nullptr;
    for (int i = 0; i < n_in; ++i) {
        if (in_sizes[i] == 8 * 64 * 64 * 64) {
            if (!wr) wr = (const float*)d_in[i];
            else if (!wi) wi = (const float*)d_in[i];
        }
    }
    float* out = (float*)d_out;

    cudaFuncSetAttribute(dft_fused_kernel, cudaFuncAttributeMaxDynamicSharedMemorySize, DFT_SMEM);
    cudaFuncSetAttribute(mix_kernel,       cudaFuncAttributeMaxDynamicSharedMemorySize, MIX_SMEM);
    cudaFuncSetAttribute(idft_mma_kernel,  cudaFuncAttributeMaxDynamicSharedMemorySize, IDFT_SMEM);

    init_basis_kernel<<<512, 256>>>();
    dft_fused_kernel<<<256, 256, DFT_SMEM>>>(q);
    mix_kernel<<<256, 256, MIX_SMEM>>>(wr, wi);
    idft_mma_kernel<<<512, 256, IDFT_SMEM>>>(out);
}

// round 16
// speedup vs baseline: 1.6618x; 1.1729x over previous
#include <cuda_runtime.h>
#include <cuda_fp16.h>
#include <cstdint>
#include <cstddef>

#define LSEQ 4096
#define LH   2048
#define NBH  128
#define CSCALE 65536.0f
#define CINV  (1.0f / 65536.0f)

// ------------------------------------------------------------- gmem scratch
__device__ __half g_Fu[64 * LH], g_Fv[64 * LH];   // fwd basis even/odd-f rows
__device__ __half g_Gte[LH * 64], g_Gto[LH * 64]; // inv basis even/odd parity
__device__ float  g_X[NBH * 64 * 128];            // [bh][e][f2]
__device__ __half g_Ce[NBH * 64 * 64], g_Co[NBH * 64 * 64];   // C * 2^16

// ------------------------------------------------------------- helpers
__device__ __forceinline__ uint32_t smem_u32(const void* p) {
    uint32_t a;
    asm("{ .reg .u64 t; cvta.to.shared.u64 t, %1; cvt.u32.u64 %0, t; }" : "=r"(a) : "l"(p));
    return a;
}
__device__ __forceinline__ void ldsm4(uint32_t* r, uint32_t addr) {
    asm volatile("ldmatrix.sync.aligned.m8n8.x4.shared.b16 {%0,%1,%2,%3}, [%4];"
                 : "=r"(r[0]), "=r"(r[1]), "=r"(r[2]), "=r"(r[3]) : "r"(addr));
}
__device__ __forceinline__ void ldsm4t(uint32_t* r, uint32_t addr) {
    asm volatile("ldmatrix.sync.aligned.m8n8.x4.trans.shared.b16 {%0,%1,%2,%3}, [%4];"
                 : "=r"(r[0]), "=r"(r[1]), "=r"(r[2]), "=r"(r[3]) : "r"(addr));
}
__device__ __forceinline__ void mma16816(float* d, const uint32_t* a, const uint32_t* b) {
    asm volatile("mma.sync.aligned.m16n8k16.row.col.f32.f16.f16.f32 "
                 "{%0,%1,%2,%3}, {%4,%5,%6,%7}, {%8,%9}, {%0,%1,%2,%3};"
                 : "+f"(d[0]), "+f"(d[1]), "+f"(d[2]), "+f"(d[3])
                 : "r"(a[0]), "r"(a[1]), "r"(a[2]), "r"(a[3]), "r"(b[0]), "r"(b[1]));
}
#define CP16(sa, gp) asm volatile("cp.async.cg.shared.global [%0], [%1], 16;" \
                                  :: "r"((uint32_t)(sa)), "l"(gp) : "memory")
#define CP_COMMIT()  asm volatile("cp.async.commit_group;" ::: "memory")
#define CP_WAIT0()   asm volatile("cp.async.wait_group 0;" ::: "memory")

// ---------------------------------------------------------------- basis init
__global__ void init_basis_kernel() {
    int idx = blockIdx.x * 256 + threadIdx.x;      // < 131072
    {   // Fu/Fv rows ru = 2*fe + c (c=0 cos, c=1 -sin), half domain
        int ru = idx >> 11, l = idx & 2047;
        int fe = ru >> 1, c = ru & 1;
        float s, cs;
        sincospif((float)((l * (2 * fe)) & 4095) / 2048.0f, &s, &cs);
        g_Fu[ru * LH + l] = __float2half(c ? -s : cs);
        sincospif((float)((l * (2 * fe + 1)) & 4095) / 2048.0f, &s, &cs);
        g_Fv[ru * LH + l] = __float2half(c ? -s : cs);
    }
    {   // Gte/Gto: [l][kk=2*fe+c], c=0 cos, c=1 +sin
        int l = idx >> 6, kk = idx & 63;
        int fe = kk >> 1, c = kk & 1;
        float s, cs;
        sincospif((float)((l * (2 * fe)) & 4095) / 2048.0f, &s, &cs);
        g_Gte[l * 64 + kk] = __float2half(c ? s : cs);
        sincospif((float)((l * (2 * fe + 1)) & 4095) / 2048.0f, &s, &cs);
        g_Gto[l * 64 + kk] = __float2half(c ? s : cs);
    }
}

// ---------------------------------------------------------------- Stage 1: DFT
// CTA = (e-half, bh), grid 256. D[128 f2, 32 e], K=2048 in 32 chunks of 64.
// 1 sync/chunk; smem 57KB -> 3 CTAs/SM.
#define D_ARR  9216                  // F array: 64 rows * 144B
#define F_STG  (2 * D_ARR)           // Fu|Fv = 18432
#define UV_ARR 5120                  // 64 rows * 80B
#define UV_STG (2 * UV_ARR)          // 10240
#define DFT_SMEM (2 * F_STG + 2 * UV_STG)   // 57344

__global__ __launch_bounds__(256, 3) void dft_fused_kernel(const float* __restrict__ q) {
    extern __shared__ char smd[];
    const uint32_t sb = smem_u32(smd);
    const int bh = blockIdx.x & 127, eh = blockIdx.x >> 7;   // e-half 0/1
    const int b = bh >> 3, h = bh & 7;
    const int t = threadIdx.x, w = t >> 5, lane = t & 31;
    const int grp = w >> 2, wr = w & 3;
    const float* qb = q + ((size_t)b * LSEQ * 8 + h) * 64 + eh * 32;

    const __half* srcF[2] = { g_Fu, g_Fv };

    const int ql = t >> 3, qe4 = (t & 7) * 4;   // 32 l rows per pass, 32 e
    float4 ra[2], rb[2];
    auto LDGQ = [&](int l0) {
        #pragma unroll
        for (int ps = 0; ps < 2; ++ps) {
            const float* p = qb + (size_t)(l0 + ql + ps * 32) * 512 + qe4;
            ra[ps] = *(const float4*)p;
            rb[ps] = *(const float4*)(p + (size_t)LH * 512);
        }
    };
    auto issueF = [&](int c, uint32_t stg) {     // 64 rows x 64 k per array
        const size_t k0 = (size_t)c * 64;
        #pragma unroll
        for (int i = 0; i < 4; ++i) {
            int arr = i >> 1;
            int idx = ((i & 1) << 8) + t;
            int row = idx >> 3, kg = (idx & 7) * 8;
            CP16(stg + arr * D_ARR + (uint32_t)row * 144 + kg * 2,
                 srcF[arr] + (size_t)row * LH + k0 + kg);
        }
        CP_COMMIT();
    };
    auto convert = [&](uint32_t uvoff) {          // u at +0, v at +UV_ARR; [64 l][32e]
        #pragma unroll
        for (int ps = 0; ps < 2; ++ps) {
            int l = ql + ps * 32;
            uint32_t ad = uvoff + (uint32_t)l * 80 + (t & 7) * 8;
            float4 a = ra[ps], bb = rb[ps];
            union { uint2 v; __half x[4]; } U, V;
            U.x[0] = __float2half(a.x + bb.x);  V.x[0] = __float2half(a.x - bb.x);
            U.x[1] = __float2half(a.y + bb.y);  V.x[1] = __float2half(a.y - bb.y);
            U.x[2] = __float2half(a.z + bb.z);  V.x[2] = __float2half(a.z - bb.z);
            U.x[3] = __float2half(a.w + bb.w);  V.x[3] = __float2half(a.w - bb.w);
            *(uint2*)(smd + ad)          = U.v;
            *(uint2*)(smd + ad + UV_ARR) = V.v;
        }
    };

    const uint32_t aoff = (uint32_t)(wr * 16 + (lane & 15)) * 144 + (lane >> 4) * 16;
    const uint32_t boff = (uint32_t)(lane & 15) * 80 + (lane >> 4) * 16;

    float acc[4][4];
    #pragma unroll
    for (int i = 0; i < 4; ++i)
        #pragma unroll
        for (int j = 0; j < 4; ++j) acc[i][j] = 0.f;

    LDGQ(0);
    issueF(0, sb);
    for (int c = 0; c < 32; ++c) {
        const uint32_t uvoff = 2 * F_STG + (uint32_t)(c & 1) * UV_STG;
        convert(uvoff);                       // writes uv(c); MMA(c-1) uses other buf
        if (c < 31) LDGQ((c + 1) * 64);       // register prefetch
        CP_WAIT0();                           // F(c) landed
        __syncthreads();                      // all warps past MMA(c-1), uv(c) visible
        if (c < 31) issueF(c + 1, sb + (uint32_t)((c + 1) & 1) * F_STG);
        const uint32_t aF = sb + (uint32_t)(c & 1) * F_STG + grp * D_ARR + aoff;
        const uint32_t bB = sb + uvoff + grp * UV_ARR + boff;
        #pragma unroll
        for (int ks = 0; ks < 4; ++ks) {
            uint32_t ah[4];
            ldsm4(ah, aF + ks * 32);
            #pragma unroll
            for (int j = 0; j < 2; ++j) {
                uint32_t bv[4];
                ldsm4t(bv, bB + ks * 1280 + j * 32);    // 1280 = 16*80
                mma16816(acc[2 * j],     ah, bv);
                mma16816(acc[2 * j + 1], ah, bv + 2);
            }
        }
    }

    const int g = lane >> 2, q4 = lane & 3;
    float* xb = g_X + (size_t)bh * 8192;
    const int r0 = wr * 16 + g, r1 = r0 + 8;
    const int f2a = 2 * r0 - (r0 & 1) + 2 * grp;
    const int f2b = 2 * r1 - (r1 & 1) + 2 * grp;
    #pragma unroll
    for (int jj = 0; jj < 4; ++jj) {
        int e0 = eh * 32 + jj * 8 + q4 * 2;
        xb[e0 * 128 + f2a]       = acc[jj][0];
        xb[(e0 + 1) * 128 + f2a] = acc[jj][1];
        xb[e0 * 128 + f2b]       = acc[jj][2];
        xb[(e0 + 1) * 128 + f2b] = acc[jj][3];
    }
}

// ---------------------------------------------------------------- Stage 2: mix
// grid 256: (h, og: 8 o, bq: 4 b). cp.async double-buffered 8-e chunks,
// 1 sync per chunk. Stage = Ws_r 16K | Ws_i 16K | Xs 16K = 48KB; 2 stages.
#define M_STG  49152
#define MIX_SMEM (2 * M_STG)     // 98304
__global__ __launch_bounds__(256, 2) void mix_kernel(const float* __restrict__ wr,
                                                     const float* __restrict__ wi) {
    extern __shared__ char sm[];
    const uint32_t sb = smem_u32(sm);
    const int h = blockIdx.x & 7, og = (blockIdx.x >> 3) & 7, bq = blockIdx.x >> 6;
    const int t = threadIdx.x;
    const int f2 = t & 31, ol = t >> 5;

    auto issue = [&](int ch, uint32_t stg) {     // chunk ch covers e = ch*8..ch*8+7
        const int e0 = ch * 8;
        // W: 64 rows (e*8+o) x 64 m, 2 arrays; 4 CP16/thread each
        #pragma unroll
        for (int i = 0; i < 4; ++i) {
            int idx = (i << 8) + t;
            int row = idx >> 4, m4 = (idx & 15) * 4;
            int e = row >> 3, o = row & 7;
            size_t g = (((size_t)h * 64 + e0 + e) * 64 + og * 8 + o) * 64 + m4;
            CP16(stg + (uint32_t)row * 256 + m4 * 4, wr + g);
            CP16(stg + 16384 + (uint32_t)row * 256 + m4 * 4, wi + g);
        }
        // X: 32 rows (b*8+e) x 128 f; 4 CP16/thread
        #pragma unroll
        for (int i = 0; i < 4; ++i) {
            int idx = (i << 8) + t;
            int row = idx >> 5, f4 = (idx & 31) * 4;
            int b = row >> 3, e = row & 7;
            int bh = (bq * 4 + b) * 8 + h;
            CP16(stg + 32768 + (uint32_t)row * 512 + f4 * 4,
                 g_X + (size_t)bh * 8192 + (e0 + e) * 128 + f4);
        }
        CP_COMMIT();
    };

    float acc[4][4];
    #pragma unroll
    for (int i = 0; i < 4; ++i)
        #pragma unroll
        for (int j = 0; j < 4; ++j) acc[i][j] = 0.f;

    issue(0, sb);
    for (int ch = 0; ch < 8; ++ch) {
        const uint32_t stg = sb + (uint32_t)(ch & 1) * M_STG;
        CP_WAIT0();
        __syncthreads();                      // chunk ch visible; all past compute(ch-1)
        if (ch < 7) issue(ch + 1, sb + (uint32_t)((ch + 1) & 1) * M_STG);
        const float* Ws_r = (const float*)(sm + (stg - sb));
        const float* Ws_i = (const float*)(sm + (stg - sb) + 16384);
        const float* Xs   = (const float*)(sm + (stg - sb) + 32768);
        #pragma unroll
        for (int e = 0; e < 8; ++e) {
            float2 w_r = *(const float2*)&Ws_r[(e * 8 + ol) * 64 + 2 * f2];
            float2 w_i = *(const float2*)&Ws_i[(e * 8 + ol) * 64 + 2 * f2];
            #pragma unroll
            for (int b = 0; b < 4; ++b) {
                float4 x = *(const float4*)&Xs[(b * 8 + e) * 128 + 4 * f2];
                acc[b][0] += x.x * w_r.x - x.y * w_i.x;
                acc[b][1] += x.x * w_i.x + x.y * w_r.x;
                acc[b][2] += x.z * w_r.y - x.w * w_i.y;
                acc[b][3] += x.z * w_i.y + x.w * w_r.y;
            }
        }
    }
    const float a0 = ((f2 == 0) ? (1.0f / 4096.0f) : (2.0f / 4096.0f)) * CSCALE;
    const float a1 = (2.0f / 4096.0f) * CSCALE;
    #pragma unroll
    for (int b = 0; b < 4; ++b) {
        size_t row = (size_t)((bq * 4 + b) * 8 + h) * 64 + og * 8 + ol;
        union { uint32_t u; __half x[2]; } p;
        p.x[0] = __float2half(a0 * acc[b][0]);
        p.x[1] = __float2half(-a0 * acc[b][1]);
        *(uint32_t*)&g_Ce[row * 64 + 2 * f2] = p.u;
        p.x[0] = __float2half(a1 * acc[b][2]);
        p.x[1] = __float2half(-a1 * acc[b][3]);
        *(uint32_t*)&g_Co[row * 64 + 2 * f2] = p.u;
    }
}

// ---------------------------------------------------------------- Stage 3: iDFT
// CTA = (bh, lq), grid 512 (R14/R15 config, measured 41us). 1 sync/chunk.
#define IJ_ARR 9216                  // 64 rows * 144B
#define IA_SZ  (2 * IJ_ARR)          // Ce|Co = 18432
#define IG_SZ  (2 * IJ_ARR)          // Gte|Gto per stage = 18432
#define IDFT_SMEM (IA_SZ + 2 * IG_SZ)   // 55296

__global__ __launch_bounds__(256, 3) void idft_mma_kernel(float* __restrict__ out) {
    extern __shared__ char smi[];
    const uint32_t sb = smem_u32(smi);
    const int bh = blockIdx.x & 127, lq = blockIdx.x >> 7;   // lq 0..3
    const int t = threadIdx.x, w = t >> 5, lane = t & 31;
    const int w4 = w & 3, wh = w >> 2;        // row group / l-half
    const size_t pC = (size_t)bh * 64 * 64;

    const __half* srcA[2] = { g_Ce + pC, g_Co + pC };
    const __half* srcG[2] = { g_Gte, g_Gto };

    auto issueG = [&](int lc, uint32_t stg) {     // 64 l rows x 64 k, 2 arrays
        const size_t lG = (size_t)lc * 64 * 64;
        #pragma unroll
        for (int i = 0; i < 4; ++i) {
            int arr = i >> 1;
            int idx = ((i & 1) << 8) + t;
            int row = idx >> 3, kg = (idx & 7) * 8;
            CP16(stg + arr * IJ_ARR + (uint32_t)row * 144 + kg * 2,
                 srcG[arr] + lG + (size_t)row * 64 + kg);
        }
    };

    // prologue: A (2 arrays) + G(lq*8), one group
    #pragma unroll
    for (int i = 0; i < 4; ++i) {
        int arr = i >> 1;
        int idx = ((i & 1) << 8) + t;
        int row = idx >> 3, kg = (idx & 7) * 8;
        CP16(sb + arr * IJ_ARR + (uint32_t)row * 144 + kg * 2,
             srcA[arr] + (size_t)row * 64 + kg);
    }
    issueG(lq * 8, sb + IA_SZ);
    CP_COMMIT();

    const uint32_t aoff = (uint32_t)(w4 * 16 + (lane & 15)) * 144 + (lane >> 4) * 16;
    uint32_t boff[2];
    #pragma unroll
    for (int jl = 0; jl < 2; ++jl)
        boff[jl] = (uint32_t)(wh * 32 + jl * 16 + (lane >> 4) * 8 + (lane & 7)) * 144
                 + ((lane >> 3) & 1) * 16;
    const int g = lane >> 2, q4 = lane & 3;

    for (int cc = 0; cc < 8; ++cc) {
        const int lc = lq * 8 + cc;
        CP_WAIT0();
        __syncthreads();          // chunk cc data visible; all warps past chunk cc-1
        if (cc < 7) {
            issueG(lc + 1, sb + IA_SZ + (uint32_t)((cc + 1) & 1) * IG_SZ);
            CP_COMMIT();
        }
        const uint32_t gst = sb + IA_SZ + (uint32_t)(cc & 1) * IG_SZ;

        float accE[4][4], accO[4][4];
        #pragma unroll
        for (int i = 0; i < 4; ++i)
            #pragma unroll
            for (int j = 0; j < 4; ++j) { accE[i][j] = 0.f; accO[i][j] = 0.f; }

        #pragma unroll
        for (int p = 0; p < 2; ++p) {
            float (*acc)[4] = p ? accO : accE;
            const uint32_t aC = sb + (uint32_t)p * IJ_ARR + aoff;
            const uint32_t gb = gst + (uint32_t)p * IJ_ARR;
            #pragma unroll
            for (int ks = 0; ks < 4; ++ks) {
                uint32_t ac[4];
                ldsm4(ac, aC + ks * 32);
                #pragma unroll
                for (int jl = 0; jl < 2; ++jl) {
                    uint32_t bh_[4];
                    ldsm4(bh_, gb + boff[jl] + ks * 32);
                    mma16816(acc[2 * jl],     ac, bh_);
                    mma16816(acc[2 * jl + 1], ac, bh_ + 2);
                }
            }
        }

        // register combine + direct stores (4-lane groups form 32B segments)
        const int r0 = w4 * 16 + g;
        float* o0 = out + ((size_t)bh * 64 + r0) * LSEQ + lc * 64 + wh * 32 + q4 * 2;
        float* o1 = o0 + (size_t)8 * LSEQ;
        #pragma unroll
        for (int jj = 0; jj < 4; ++jj) {
            float e0 = accE[jj][0], e1 = accE[jj][1], o0v = accO[jj][0], o1v = accO[jj][1];
            float e2 = accE[jj][2], e3 = accE[jj][3], o2v = accO[jj][2], o3v = accO[jj][3];
            *(float2*)(o0 + jj * 8)      = make_float2((e0 + o0v) * CINV, (e1 + o1v) * CINV);
            *(float2*)(o0 + LH + jj * 8) = make_float2((e0 - o0v) * CINV, (e1 - o1v) * CINV);
            *(float2*)(o1 + jj * 8)      = make_float2((e2 + o2v) * CINV, (e3 + o3v) * CINV);
            *(float2*)(o1 + LH + jj * 8) = make_float2((e2 - o2v) * CINV, (e3 - o3v) * CINV);
        }
    }
}

// ---------------------------------------------------------------------------
extern "C" void kernel_launch(void* const* d_in, const int* in_sizes, int n_in,
                              void* d_out, int out_size) {
    const float* q = (const float*)d_in[0];
    const float* wr = nullptr;
    const float* wi = nullptr;
    for (int i = 0; i < n_in; ++i) {
        if (in_sizes[i] == 8 * 64 * 64 * 64) {
            if (!wr) wr = (const float*)d_in[i];
            else if (!wi) wi = (const float*)d_in[i];
        }
    }
    float* out = (float*)d_out;

    cudaFuncSetAttribute(dft_fused_kernel, cudaFuncAttributeMaxDynamicSharedMemorySize, DFT_SMEM);
    cudaFuncSetAttribute(mix_kernel,       cudaFuncAttributeMaxDynamicSharedMemorySize, MIX_SMEM);
    cudaFuncSetAttribute(idft_mma_kernel,  cudaFuncAttributeMaxDynamicSharedMemorySize, IDFT_SMEM);

    init_basis_kernel<<<512, 256>>>();
    dft_fused_kernel<<<256, 256, DFT_SMEM>>>(q);
    mix_kernel<<<256, 256, MIX_SMEM>>>(wr, wi);
    idft_mma_kernel<<<512, 256, IDFT_SMEM>>>(out);
}